// round 2
// baseline (speedup 1.0000x reference)
#include <cuda_runtime.h>
#include <math.h>

#define NN   100000
#define EE   1600000
#define C    32
#define KK   5
#define L1   (KK*C)          // 160
#define EPSV 1e-15f
#define BNE  1e-5f

// ------------------------- device scratch (no allocs) -------------------------
__device__ float  g_lin1[(size_t)NN*C];
__device__ float  g_lins[(size_t)NN*C];
__device__ float  g_lin2[(size_t)NN*C];
__device__ float  g_z1 [(size_t)NN*L1];
__device__ float  g_zs [(size_t)NN*C];
__device__ float  g_z2 [(size_t)NN*L1];
__device__ float  g_y1 [(size_t)NN*C];
__device__ float  g_ys [(size_t)NN*C];
__device__ float  g_y2 [(size_t)NN*C];
__device__ float  g_h1 [(size_t)NN*C];
__device__ int    g_cnt[NN];
__device__ int    g_ptr[NN+1];
__device__ int    g_pos[NN];
__device__ int    g_bsum[128];
__device__ float  g_stat[8*C];     // [sum_y1, sq_y1, sum_ys, sq_ys, sum_y2, sq_y2, -, -]
__device__ float  g_bns[6*C];      // [sc1, sh1, scs, shs, sc2, sh2]
__device__ float4 g_m1[(size_t)2*EE];   // per CSR edge: {src, ws, w1_0, w1_1},{w1_2, w1_3, w1_4, 0}
__device__ float4 g_m2[(size_t)2*EE];   // per CSR edge: {src, w2_0, w2_1, w2_2},{w2_3, w2_4, 0, 0}

// ------------------------------- zero scratch --------------------------------
__global__ void k_zero() {
    int i = blockIdx.x * blockDim.x + threadIdx.x;
    if (i < NN)   g_cnt[i] = 0;
    if (i < 8*C)  g_stat[i] = 0.f;
}

// --------------------- prepA: lin1 = x@root1+b1, lins = x@roots+bs -----------
__global__ void k_prepA(const float* __restrict__ x, const float* __restrict__ root1,
                        const float* __restrict__ b1, const float* __restrict__ roots,
                        const float* __restrict__ bs) {
    __shared__ float Wsh[C][64];
    __shared__ float bsh[64];
    __shared__ float xsh[32][C+1];
    int tid = threadIdx.x;
    for (int idx = tid; idx < C*64; idx += 256) {
        int j = idx >> 6, c = idx & 63;
        Wsh[j][c] = (c < 32) ? root1[j*C + c] : roots[j*C + (c - 32)];
    }
    if (tid < 64) bsh[tid] = (tid < 32) ? b1[tid] : bs[tid - 32];
    int n0 = blockIdx.x * 32;
    for (int idx = tid; idx < 32*C; idx += 256) {
        int ln = idx >> 5, i = idx & 31;
        int n = n0 + ln;
        xsh[ln][i] = (n < NN) ? x[(size_t)n*C + i] : 0.f;
    }
    __syncthreads();
    int warp = tid >> 5, lane = tid & 31;
    for (int t = warp; t < 64; t += 8) {
        int ln = t >> 1, half = t & 1;
        int n = n0 + ln;
        if (n >= NN) continue;
        int c = half*32 + lane;
        float acc = bsh[c];
        #pragma unroll
        for (int j = 0; j < C; j++) acc += xsh[ln][j] * Wsh[j][c];
        if (half == 0) g_lin1[(size_t)n*C + lane] = acc;
        else           g_lins[(size_t)n*C + lane] = acc;
    }
}

// ------------------------------ CSR build ------------------------------------
__global__ void k_count(const int* __restrict__ ei) {
    int e = blockIdx.x * 256 + threadIdx.x;
    if (e < EE) atomicAdd(&g_cnt[ei[EE + e]], 1);
}

__global__ void k_scan1() {
    __shared__ int sd[1024];
    int tid = threadIdx.x;
    int i = blockIdx.x * 1024 + tid;
    int v = (i < NN) ? g_cnt[i] : 0;
    sd[tid] = v; __syncthreads();
    for (int off = 1; off < 1024; off <<= 1) {
        int t = (tid >= off) ? sd[tid - off] : 0;
        __syncthreads();
        sd[tid] += t; __syncthreads();
    }
    if (i < NN) g_ptr[i] = sd[tid] - v;           // block-local exclusive
    if (tid == 1023) g_bsum[blockIdx.x] = sd[1023];
}

__global__ void k_scan2(int nb) {
    if (threadIdx.x == 0) {
        int run = 0;
        for (int b = 0; b < nb; b++) { int t = g_bsum[b]; g_bsum[b] = run; run += t; }
    }
}

__global__ void k_scan3() {
    int i = blockIdx.x * 256 + threadIdx.x;
    if (i < NN) {
        int p = g_ptr[i] + g_bsum[i >> 10];
        g_ptr[i] = p; g_pos[i] = p;
    }
    if (i == 0) g_ptr[NN] = EE;
}

// ---- fill: scatter edges into CSR; precompute Gaussian weights per edge -----
__device__ __forceinline__ float gauss_term(float a, float m, float s) {
    float d = a - m;
    return d * d / (EPSV + s * s);
}

__global__ void k_fill(const int* __restrict__ ei, const float* __restrict__ attr,
                       const float* __restrict__ mu1, const float* __restrict__ sg1,
                       const float* __restrict__ mu2, const float* __restrict__ sg2,
                       const float* __restrict__ mus, const float* __restrict__ sgs) {
    int e = blockIdx.x * 256 + threadIdx.x;
    if (e >= EE) return;
    int s = ei[e], d = ei[EE + e];
    float a0 = attr[3*e], a1 = attr[3*e + 1], a2 = attr[3*e + 2];
    float w1[KK], w2[KK];
    #pragma unroll
    for (int k = 0; k < KK; k++) {
        float t1 = gauss_term(a0, __ldg(mu1 + 3*k    ), __ldg(sg1 + 3*k    ))
                 + gauss_term(a1, __ldg(mu1 + 3*k + 1), __ldg(sg1 + 3*k + 1))
                 + gauss_term(a2, __ldg(mu1 + 3*k + 2), __ldg(sg1 + 3*k + 2));
        w1[k] = __expf(-0.5f * t1);
        float t2 = gauss_term(a0, __ldg(mu2 + 3*k    ), __ldg(sg2 + 3*k    ))
                 + gauss_term(a1, __ldg(mu2 + 3*k + 1), __ldg(sg2 + 3*k + 1))
                 + gauss_term(a2, __ldg(mu2 + 3*k + 2), __ldg(sg2 + 3*k + 2));
        w2[k] = __expf(-0.5f * t2);
    }
    float ts = gauss_term(a0, __ldg(mus), __ldg(sgs))
             + gauss_term(a1, __ldg(mus + 1), __ldg(sgs + 1))
             + gauss_term(a2, __ldg(mus + 2), __ldg(sgs + 2));
    float ws = __expf(-0.5f * ts);

    int p = atomicAdd(&g_pos[d], 1);
    g_m1[2*(size_t)p]     = make_float4(__int_as_float(s), ws, w1[0], w1[1]);
    g_m1[2*(size_t)p + 1] = make_float4(w1[2], w1[3], w1[4], 0.f);
    g_m2[2*(size_t)p]     = make_float4(__int_as_float(s), w2[0], w2[1], w2[2]);
    g_m2[2*(size_t)p + 1] = make_float4(w2[3], w2[4], 0.f, 0.f);
}

// ------------- edge pass 1 (conv1 K=5 + shortcut K=1, fused): gather x -------
__global__ void k_edge1(const float* __restrict__ x) {
    int n = blockIdx.x * 8 + (threadIdx.x >> 5);
    if (n >= NN) return;
    int lane = threadIdx.x & 31;
    int beg = g_ptr[n], end = g_ptr[n + 1];
    float a0 = 0.f, a1 = 0.f, a2 = 0.f, a3 = 0.f, a4 = 0.f, as_ = 0.f;
    for (int j = beg; j < end; j++) {
        float4 ma = g_m1[2*(size_t)j];
        float4 mb = g_m1[2*(size_t)j + 1];
        int s = __float_as_int(ma.x);
        float xv = __ldg(x + (size_t)s*C + lane);
        as_ += ma.y * xv;
        a0  += ma.z * xv;  a1 += ma.w * xv;
        a2  += mb.x * xv;  a3 += mb.y * xv;  a4 += mb.z * xv;
    }
    float inv = 1.f / fmaxf((float)(end - beg), 1.f);
    size_t b = (size_t)n * L1 + lane;
    g_z1[b]       = a0 * inv;
    g_z1[b + 32]  = a1 * inv;
    g_z1[b + 64]  = a2 * inv;
    g_z1[b + 96]  = a3 * inv;
    g_z1[b + 128] = a4 * inv;
    g_zs[(size_t)n*C + lane] = as_ * inv;
}

// -------- postA: y1 = z1 @ B1 + lin1 ; ys = zs @ gs + lins -------------------
__global__ void k_postA(const float* __restrict__ g1, const float* __restrict__ gs) {
    __shared__ float B1[L1][C];      // remapped g1:  B1[k*32+i][o] = g1[i][k*32+o]
    __shared__ float Bs[C][C];
    __shared__ float z1sh[16][L1];
    __shared__ float zssh[16][C];
    int tid = threadIdx.x;
    for (int idx = tid; idx < C*L1; idx += 256) {
        int i = idx / L1, r = idx % L1;
        int k = r >> 5, c = r & 31;
        B1[k*32 + i][c] = g1[idx];
    }
    for (int idx = tid; idx < C*C; idx += 256)
        Bs[idx >> 5][idx & 31] = gs[idx];
    int n0 = blockIdx.x * 16;
    for (int idx = tid; idx < 16*L1; idx += 256) {
        int ln = idx / L1, j = idx % L1;
        int n = n0 + ln;
        z1sh[ln][j] = (n < NN) ? g_z1[(size_t)n*L1 + j] : 0.f;
    }
    for (int idx = tid; idx < 16*C; idx += 256) {
        int ln = idx >> 5, j = idx & 31;
        int n = n0 + ln;
        zssh[ln][j] = (n < NN) ? g_zs[(size_t)n*C + j] : 0.f;
    }
    __syncthreads();
    int warp = tid >> 5, lane = tid & 31;
    for (int t = warp; t < 32; t += 8) {       // t<16: heavy (y1, node t); t>=16: light (ys)
        if (t < 16) {
            int n = n0 + t; if (n >= NN) continue;
            float acc = 0.f;
            #pragma unroll
            for (int j = 0; j < L1; j++) acc += z1sh[t][j] * B1[j][lane];
            g_y1[(size_t)n*C + lane] = acc + g_lin1[(size_t)n*C + lane];
        } else {
            int ln = t - 16;
            int n = n0 + ln; if (n >= NN) continue;
            float acc = 0.f;
            #pragma unroll
            for (int j = 0; j < C; j++) acc += zssh[ln][j] * Bs[j][lane];
            g_ys[(size_t)n*C + lane] = acc + g_lins[(size_t)n*C + lane];
        }
    }
}

// ------------------------ BN batch stats (y1, ys) ----------------------------
__global__ void k_stat1() {
    __shared__ float red[4][8][33];
    int tid = threadIdx.x, lane = tid & 31, warp = tid >> 5;
    float s1 = 0.f, q1 = 0.f, ss = 0.f, qs = 0.f;
    for (int n = blockIdx.x*8 + warp; n < NN; n += gridDim.x*8) {
        float v = g_y1[(size_t)n*C + lane]; s1 += v; q1 += v*v;
        float u = g_ys[(size_t)n*C + lane]; ss += u; qs += u*u;
    }
    red[0][warp][lane] = s1; red[1][warp][lane] = q1;
    red[2][warp][lane] = ss; red[3][warp][lane] = qs;
    __syncthreads();
    if (warp < 4) {
        float t = 0.f;
        #pragma unroll
        for (int w = 0; w < 8; w++) t += red[warp][w][lane];
        atomicAdd(&g_stat[warp*32 + lane], t);
    }
}

__global__ void k_finA(const float* __restrict__ gam1, const float* __restrict__ bet1,
                       const float* __restrict__ gams, const float* __restrict__ bets) {
    int t = threadIdx.x;
    const float invn = 1.f / (float)NN;
    if (t < 32) {
        float m = g_stat[t] * invn;
        float v = g_stat[32 + t] * invn - m*m;
        float sc = gam1[t] * rsqrtf(v + BNE);
        g_bns[t] = sc; g_bns[32 + t] = bet1[t] - m*sc;
    } else if (t < 64) {
        int c = t - 32;
        float m = g_stat[64 + c] * invn;
        float v = g_stat[96 + c] * invn - m*m;
        float sc = gams[c] * rsqrtf(v + BNE);
        g_bns[64 + c] = sc; g_bns[96 + c] = bets[c] - m*sc;
    }
}

// --------- prepB: h1 = elu(BN1(y1)); lin2 = h1@root2 + b2; store h1 ----------
__global__ void k_prepB(const float* __restrict__ root2, const float* __restrict__ b2) {
    __shared__ float Wsh[C][C];
    __shared__ float hsh[32][C+1];
    __shared__ float scs[C], shs[C], b2s[C];
    int tid = threadIdx.x;
    for (int idx = tid; idx < C*C; idx += 256)
        Wsh[idx >> 5][idx & 31] = root2[idx];
    if (tid < 32) { scs[tid] = g_bns[tid]; shs[tid] = g_bns[32 + tid]; b2s[tid] = b2[tid]; }
    __syncthreads();
    int n0 = blockIdx.x * 32;
    for (int idx = tid; idx < 32*C; idx += 256) {
        int ln = idx >> 5, i = idx & 31;
        int n = n0 + ln;
        float h = 0.f;
        if (n < NN) {
            float v = g_y1[(size_t)n*C + i] * scs[i] + shs[i];
            h = (v > 0.f) ? v : expm1f(v);
            g_h1[(size_t)n*C + i] = h;
        }
        hsh[ln][i] = h;
    }
    __syncthreads();
    int warp = tid >> 5, lane = tid & 31;
    for (int t = warp; t < 32; t += 8) {
        int n = n0 + t;
        if (n >= NN) continue;
        float acc = b2s[lane];
        #pragma unroll
        for (int j = 0; j < C; j++) acc += hsh[t][j] * Wsh[j][lane];
        g_lin2[(size_t)n*C + lane] = acc;
    }
}

// ------------------------ edge pass 2 (conv2 K=5): gather h1 -----------------
__global__ void k_edge2() {
    int n = blockIdx.x * 8 + (threadIdx.x >> 5);
    if (n >= NN) return;
    int lane = threadIdx.x & 31;
    int beg = g_ptr[n], end = g_ptr[n + 1];
    float a0 = 0.f, a1 = 0.f, a2 = 0.f, a3 = 0.f, a4 = 0.f;
    for (int j = beg; j < end; j++) {
        float4 ma = g_m2[2*(size_t)j];
        float4 mb = g_m2[2*(size_t)j + 1];
        int s = __float_as_int(ma.x);
        float hv = __ldg(&g_h1[(size_t)s*C + lane]);
        a0 += ma.y * hv; a1 += ma.z * hv; a2 += ma.w * hv;
        a3 += mb.x * hv; a4 += mb.y * hv;
    }
    float inv = 1.f / fmaxf((float)(end - beg), 1.f);
    size_t b = (size_t)n * L1 + lane;
    g_z2[b]       = a0 * inv;
    g_z2[b + 32]  = a1 * inv;
    g_z2[b + 64]  = a2 * inv;
    g_z2[b + 96]  = a3 * inv;
    g_z2[b + 128] = a4 * inv;
}

// ---------------------- postB: y2 = z2 @ B2 + lin2 ---------------------------
__global__ void k_postB(const float* __restrict__ g2) {
    __shared__ float B2[L1][C];
    __shared__ float zsh[16][L1];
    int tid = threadIdx.x;
    for (int idx = tid; idx < C*L1; idx += 256) {
        int i = idx / L1, r = idx % L1;
        int k = r >> 5, c = r & 31;
        B2[k*32 + i][c] = g2[idx];
    }
    int n0 = blockIdx.x * 16;
    for (int idx = tid; idx < 16*L1; idx += 256) {
        int ln = idx / L1, j = idx % L1;
        int n = n0 + ln;
        zsh[ln][j] = (n < NN) ? g_z2[(size_t)n*L1 + j] : 0.f;
    }
    __syncthreads();
    int warp = tid >> 5, lane = tid & 31;
    for (int t = warp; t < 16; t += 8) {
        int n = n0 + t;
        if (n >= NN) continue;
        float acc = 0.f;
        #pragma unroll
        for (int j = 0; j < L1; j++) acc += zsh[t][j] * B2[j][lane];
        g_y2[(size_t)n*C + lane] = acc + g_lin2[(size_t)n*C + lane];
    }
}

__global__ void k_stat2() {
    __shared__ float red[2][8][33];
    int tid = threadIdx.x, lane = tid & 31, warp = tid >> 5;
    float s2 = 0.f, q2 = 0.f;
    for (int n = blockIdx.x*8 + warp; n < NN; n += gridDim.x*8) {
        float v = g_y2[(size_t)n*C + lane]; s2 += v; q2 += v*v;
    }
    red[0][warp][lane] = s2; red[1][warp][lane] = q2;
    __syncthreads();
    if (warp < 2) {
        float t = 0.f;
        #pragma unroll
        for (int w = 0; w < 8; w++) t += red[warp][w][lane];
        atomicAdd(&g_stat[128 + warp*32 + lane], t);
    }
}

__global__ void k_finB(const float* __restrict__ gam2, const float* __restrict__ bet2) {
    int t = threadIdx.x;
    if (t < 32) {
        const float invn = 1.f / (float)NN;
        float m = g_stat[128 + t] * invn;
        float v = g_stat[160 + t] * invn - m*m;
        float sc = gam2[t] * rsqrtf(v + BNE);
        g_bns[128 + t] = sc; g_bns[160 + t] = bet2[t] - m*sc;
    }
}

// ------------------- final: out = elu(BN2(y2) + BNs(ys)) ---------------------
__global__ void k_final(float* __restrict__ out) {
    int i = blockIdx.x * 256 + threadIdx.x;
    if (i >= NN*C) return;
    int c = i & 31;
    float v2 = g_y2[i] * g_bns[128 + c] + g_bns[160 + c];
    float vs = g_ys[i] * g_bns[64 + c]  + g_bns[96 + c];
    float h = v2 + vs;
    out[i] = (h > 0.f) ? h : expm1f(h);
}

// ------------------------------------------------------------------------------
extern "C" void kernel_launch(void* const* d_in, const int* in_sizes, int n_in,
                              void* d_out, int out_size) {
    (void)in_sizes; (void)n_in; (void)out_size;
    const float* x     = (const float*)d_in[0];
    const int*   ei    = (const int*)  d_in[1];
    const float* attr  = (const float*)d_in[2];
    const float* g1    = (const float*)d_in[3];
    const float* mu1   = (const float*)d_in[4];
    const float* sg1   = (const float*)d_in[5];
    const float* root1 = (const float*)d_in[6];
    const float* b1    = (const float*)d_in[7];
    const float* gam1  = (const float*)d_in[8];
    const float* bet1  = (const float*)d_in[9];
    const float* g2    = (const float*)d_in[10];
    const float* mu2   = (const float*)d_in[11];
    const float* sg2   = (const float*)d_in[12];
    const float* root2 = (const float*)d_in[13];
    const float* b2    = (const float*)d_in[14];
    const float* gam2  = (const float*)d_in[15];
    const float* bet2  = (const float*)d_in[16];
    const float* gs    = (const float*)d_in[17];
    const float* mus   = (const float*)d_in[18];
    const float* sgs   = (const float*)d_in[19];
    const float* roots = (const float*)d_in[20];
    const float* bs    = (const float*)d_in[21];
    const float* gams  = (const float*)d_in[22];
    const float* bets  = (const float*)d_in[23];
    float* out = (float*)d_out;

    const int nb_scan = (NN + 1023) / 1024;

    k_zero <<<(NN + 255)/256, 256>>>();
    k_prepA<<<(NN + 31)/32,   256>>>(x, root1, b1, roots, bs);
    k_count<<<(EE + 255)/256, 256>>>(ei);
    k_scan1<<<nb_scan, 1024>>>();
    k_scan2<<<1, 32>>>(nb_scan);
    k_scan3<<<(NN + 255)/256, 256>>>();
    k_fill <<<(EE + 255)/256, 256>>>(ei, attr, mu1, sg1, mu2, sg2, mus, sgs);
    k_edge1<<<(NN + 7)/8,     256>>>(x);
    k_postA<<<(NN + 15)/16,   256>>>(g1, gs);
    k_stat1<<<240, 256>>>();
    k_finA <<<1, 64>>>(gam1, bet1, gams, bets);
    k_prepB<<<(NN + 31)/32,   256>>>(root2, b2);
    k_edge2<<<(NN + 7)/8,     256>>>();
    k_postB<<<(NN + 15)/16,   256>>>(g2);
    k_stat2<<<240, 256>>>();
    k_finB <<<1, 32>>>(gam2, bet2);
    k_final<<<(NN*C + 255)/256, 256>>>(out);
}

// round 3
// speedup vs baseline: 1.2604x; 1.2604x over previous
#include <cuda_runtime.h>
#include <math.h>

#define NN   100000
#define EE   1600000
#define C    32
#define KK   5
#define L1   (KK*C)          // 160
#define EPSV 1e-15f
#define BNE  1e-5f

// ------------------------- device scratch (no allocs) -------------------------
__device__ float  g_lin1[(size_t)NN*C];
__device__ float  g_lins[(size_t)NN*C];
__device__ float  g_lin2[(size_t)NN*C];
__device__ float  g_z1 [(size_t)NN*L1];
__device__ float  g_zs [(size_t)NN*C];
__device__ float  g_z2 [(size_t)NN*L1];
__device__ float  g_y1 [(size_t)NN*C];
__device__ float  g_ys [(size_t)NN*C];
__device__ float  g_y2 [(size_t)NN*C];
__device__ float  g_h1 [(size_t)NN*C];
__device__ int    g_cnt[NN];
__device__ int    g_ptr[NN+1];
__device__ int    g_pos[NN];
__device__ int    g_bsum[128];
__device__ float  g_stat[8*C];     // [sum_y1, sq_y1, sum_ys, sq_ys, sum_y2, sq_y2, -, -]
__device__ float  g_bns[6*C];      // [sc1, sh1, scs, shs, sc2, sh2]
__device__ float4 g_m1[(size_t)2*EE];   // per CSR edge: {src, ws, w1_0, w1_1},{w1_2, w1_3, w1_4, 0}
__device__ float4 g_m2[(size_t)2*EE];   // per CSR edge: {src, w2_0, w2_1, w2_2},{w2_3, w2_4, 0, 0}

// ------------------------------- zero scratch --------------------------------
__global__ void k_zero() {
    int i = blockIdx.x * blockDim.x + threadIdx.x;
    if (i < NN)   g_cnt[i] = 0;
    if (i < 8*C)  g_stat[i] = 0.f;
}

// --------------------- prepA: lin1 = x@root1+b1, lins = x@roots+bs -----------
// Register-blocked: thread = 1 node x 8 cols, W in smem, x via LDG.128
__global__ void k_prepA(const float* __restrict__ x, const float* __restrict__ root1,
                        const float* __restrict__ b1, const float* __restrict__ roots,
                        const float* __restrict__ bs) {
    __shared__ float W1[C][C];
    __shared__ float Ws[C][C];
    int tid = threadIdx.x;
    for (int idx = tid; idx < C*C; idx += 256) {
        W1[idx >> 5][idx & 31] = root1[idx];
        Ws[idx >> 5][idx & 31] = roots[idx];
    }
    __syncthreads();
    int n = blockIdx.x * 64 + (tid >> 2);
    if (n >= NN) return;
    int q = (tid & 3) * 8;
    float a1_[8], as_[8];
    {
        float4 ba = __ldg((const float4*)(b1 + q));
        float4 bb = __ldg((const float4*)(b1 + q + 4));
        a1_[0]=ba.x; a1_[1]=ba.y; a1_[2]=ba.z; a1_[3]=ba.w;
        a1_[4]=bb.x; a1_[5]=bb.y; a1_[6]=bb.z; a1_[7]=bb.w;
        float4 ca = __ldg((const float4*)(bs + q));
        float4 cb = __ldg((const float4*)(bs + q + 4));
        as_[0]=ca.x; as_[1]=ca.y; as_[2]=ca.z; as_[3]=ca.w;
        as_[4]=cb.x; as_[5]=cb.y; as_[6]=cb.z; as_[7]=cb.w;
    }
    const float* xr = x + (size_t)n * C;
    #pragma unroll
    for (int j = 0; j < C; j += 4) {
        float4 xv = __ldg((const float4*)(xr + j));
        #pragma unroll
        for (int jj = 0; jj < 4; jj++) {
            float s = (&xv.x)[jj];
            float4 wa = *(const float4*)&W1[j + jj][q];
            float4 wb = *(const float4*)&W1[j + jj][q + 4];
            a1_[0] += s*wa.x; a1_[1] += s*wa.y; a1_[2] += s*wa.z; a1_[3] += s*wa.w;
            a1_[4] += s*wb.x; a1_[5] += s*wb.y; a1_[6] += s*wb.z; a1_[7] += s*wb.w;
            float4 va = *(const float4*)&Ws[j + jj][q];
            float4 vb = *(const float4*)&Ws[j + jj][q + 4];
            as_[0] += s*va.x; as_[1] += s*va.y; as_[2] += s*va.z; as_[3] += s*va.w;
            as_[4] += s*vb.x; as_[5] += s*vb.y; as_[6] += s*vb.z; as_[7] += s*vb.w;
        }
    }
    size_t b = (size_t)n * C + q;
    *(float4*)(g_lin1 + b)     = make_float4(a1_[0], a1_[1], a1_[2], a1_[3]);
    *(float4*)(g_lin1 + b + 4) = make_float4(a1_[4], a1_[5], a1_[6], a1_[7]);
    *(float4*)(g_lins + b)     = make_float4(as_[0], as_[1], as_[2], as_[3]);
    *(float4*)(g_lins + b + 4) = make_float4(as_[4], as_[5], as_[6], as_[7]);
}

// ------------------------------ CSR build ------------------------------------
__global__ void k_count(const int* __restrict__ ei) {
    int e = blockIdx.x * 256 + threadIdx.x;
    if (e < EE) atomicAdd(&g_cnt[ei[EE + e]], 1);
}

__global__ void k_scan1() {
    __shared__ int sd[1024];
    int tid = threadIdx.x;
    int i = blockIdx.x * 1024 + tid;
    int v = (i < NN) ? g_cnt[i] : 0;
    sd[tid] = v; __syncthreads();
    for (int off = 1; off < 1024; off <<= 1) {
        int t = (tid >= off) ? sd[tid - off] : 0;
        __syncthreads();
        sd[tid] += t; __syncthreads();
    }
    if (i < NN) g_ptr[i] = sd[tid] - v;           // block-local exclusive
    if (tid == 1023) g_bsum[blockIdx.x] = sd[1023];
}

__global__ void k_scan2(int nb) {
    if (threadIdx.x == 0) {
        int run = 0;
        for (int b = 0; b < nb; b++) { int t = g_bsum[b]; g_bsum[b] = run; run += t; }
    }
}

__global__ void k_scan3() {
    int i = blockIdx.x * 256 + threadIdx.x;
    if (i < NN) {
        int p = g_ptr[i] + g_bsum[i >> 10];
        g_ptr[i] = p; g_pos[i] = p;
    }
    if (i == 0) g_ptr[NN] = EE;
}

// ---- fill: scatter edges into CSR; precompute Gaussian weights per edge -----
__device__ __forceinline__ float gauss_term(float a, float m, float s) {
    float d = a - m;
    return d * d / (EPSV + s * s);
}

__global__ void k_fill(const int* __restrict__ ei, const float* __restrict__ attr,
                       const float* __restrict__ mu1, const float* __restrict__ sg1,
                       const float* __restrict__ mu2, const float* __restrict__ sg2,
                       const float* __restrict__ mus, const float* __restrict__ sgs) {
    int e = blockIdx.x * 256 + threadIdx.x;
    if (e >= EE) return;
    int s = ei[e], d = ei[EE + e];
    float a0 = attr[3*e], a1 = attr[3*e + 1], a2 = attr[3*e + 2];
    float w1[KK], w2[KK];
    #pragma unroll
    for (int k = 0; k < KK; k++) {
        float t1 = gauss_term(a0, __ldg(mu1 + 3*k    ), __ldg(sg1 + 3*k    ))
                 + gauss_term(a1, __ldg(mu1 + 3*k + 1), __ldg(sg1 + 3*k + 1))
                 + gauss_term(a2, __ldg(mu1 + 3*k + 2), __ldg(sg1 + 3*k + 2));
        w1[k] = __expf(-0.5f * t1);
        float t2 = gauss_term(a0, __ldg(mu2 + 3*k    ), __ldg(sg2 + 3*k    ))
                 + gauss_term(a1, __ldg(mu2 + 3*k + 1), __ldg(sg2 + 3*k + 1))
                 + gauss_term(a2, __ldg(mu2 + 3*k + 2), __ldg(sg2 + 3*k + 2));
        w2[k] = __expf(-0.5f * t2);
    }
    float ts = gauss_term(a0, __ldg(mus), __ldg(sgs))
             + gauss_term(a1, __ldg(mus + 1), __ldg(sgs + 1))
             + gauss_term(a2, __ldg(mus + 2), __ldg(sgs + 2));
    float ws = __expf(-0.5f * ts);

    int p = atomicAdd(&g_pos[d], 1);
    g_m1[2*(size_t)p]     = make_float4(__int_as_float(s), ws, w1[0], w1[1]);
    g_m1[2*(size_t)p + 1] = make_float4(w1[2], w1[3], w1[4], 0.f);
    g_m2[2*(size_t)p]     = make_float4(__int_as_float(s), w2[0], w2[1], w2[2]);
    g_m2[2*(size_t)p + 1] = make_float4(w2[3], w2[4], 0.f, 0.f);
}

// ------------- edge pass 1 (conv1 K=5 + shortcut K=1, fused): gather x -------
// unroll-4 with front-batched independent loads to get MLP ~8 on meta + gather
__global__ void k_edge1(const float* __restrict__ x) {
    int n = blockIdx.x * 8 + (threadIdx.x >> 5);
    if (n >= NN) return;
    int lane = threadIdx.x & 31;
    int beg = g_ptr[n], end = g_ptr[n + 1];
    float a0 = 0.f, a1 = 0.f, a2 = 0.f, a3 = 0.f, a4 = 0.f, aS = 0.f;
    int j = beg;
    for (; j + 4 <= end; j += 4) {
        float4 ma[4], mb[4];
        #pragma unroll
        for (int u = 0; u < 4; u++) {
            ma[u] = __ldg(&g_m1[2*(size_t)(j + u)]);
            mb[u] = __ldg(&g_m1[2*(size_t)(j + u) + 1]);
        }
        float xv[4];
        #pragma unroll
        for (int u = 0; u < 4; u++)
            xv[u] = __ldg(x + (size_t)__float_as_int(ma[u].x)*C + lane);
        #pragma unroll
        for (int u = 0; u < 4; u++) {
            aS += ma[u].y * xv[u];
            a0 += ma[u].z * xv[u];  a1 += ma[u].w * xv[u];
            a2 += mb[u].x * xv[u];  a3 += mb[u].y * xv[u];  a4 += mb[u].z * xv[u];
        }
    }
    for (; j < end; j++) {
        float4 ma = __ldg(&g_m1[2*(size_t)j]);
        float4 mb = __ldg(&g_m1[2*(size_t)j + 1]);
        float xv = __ldg(x + (size_t)__float_as_int(ma.x)*C + lane);
        aS += ma.y * xv;
        a0 += ma.z * xv;  a1 += ma.w * xv;
        a2 += mb.x * xv;  a3 += mb.y * xv;  a4 += mb.z * xv;
    }
    float inv = 1.f / fmaxf((float)(end - beg), 1.f);
    size_t b = (size_t)n * L1 + lane;
    g_z1[b]       = a0 * inv;
    g_z1[b + 32]  = a1 * inv;
    g_z1[b + 64]  = a2 * inv;
    g_z1[b + 96]  = a3 * inv;
    g_z1[b + 128] = a4 * inv;
    g_zs[(size_t)n*C + lane] = aS * inv;
}

// -------- postA: y1 = z1 @ B1 + lin1 ; ys = zs @ gs + lins -------------------
// Register-blocked: thread = 1 node x 8 cols
__global__ void k_postA(const float* __restrict__ g1, const float* __restrict__ gs) {
    __shared__ float B1[L1][C];      // B1[k*32+i][o] = g1[i][k*32+o]
    __shared__ float Bs[C][C];
    int tid = threadIdx.x;
    for (int idx = tid; idx < C*L1; idx += 256) {
        int i = idx / L1, r = idx % L1;
        int k = r >> 5, c = r & 31;
        B1[k*32 + i][c] = g1[idx];
    }
    for (int idx = tid; idx < C*C; idx += 256)
        Bs[idx >> 5][idx & 31] = gs[idx];
    __syncthreads();
    int n = blockIdx.x * 64 + (tid >> 2);
    if (n >= NN) return;
    int q = (tid & 3) * 8;
    float acc[8] = {0,0,0,0,0,0,0,0};
    const float* zr = g_z1 + (size_t)n * L1;
    #pragma unroll
    for (int j = 0; j < L1; j += 4) {
        float4 zv = __ldg((const float4*)(zr + j));
        #pragma unroll
        for (int jj = 0; jj < 4; jj++) {
            float s = (&zv.x)[jj];
            float4 wa = *(const float4*)&B1[j + jj][q];
            float4 wb = *(const float4*)&B1[j + jj][q + 4];
            acc[0] += s*wa.x; acc[1] += s*wa.y; acc[2] += s*wa.z; acc[3] += s*wa.w;
            acc[4] += s*wb.x; acc[5] += s*wb.y; acc[6] += s*wb.z; acc[7] += s*wb.w;
        }
    }
    float accs[8] = {0,0,0,0,0,0,0,0};
    const float* zsr = g_zs + (size_t)n * C;
    #pragma unroll
    for (int j = 0; j < C; j += 4) {
        float4 zv = __ldg((const float4*)(zsr + j));
        #pragma unroll
        for (int jj = 0; jj < 4; jj++) {
            float s = (&zv.x)[jj];
            float4 wa = *(const float4*)&Bs[j + jj][q];
            float4 wb = *(const float4*)&Bs[j + jj][q + 4];
            accs[0] += s*wa.x; accs[1] += s*wa.y; accs[2] += s*wa.z; accs[3] += s*wa.w;
            accs[4] += s*wb.x; accs[5] += s*wb.y; accs[6] += s*wb.z; accs[7] += s*wb.w;
        }
    }
    size_t b = (size_t)n * C + q;
    float4 la = __ldg((const float4*)(g_lin1 + b));
    float4 lb = __ldg((const float4*)(g_lin1 + b + 4));
    *(float4*)(g_y1 + b)     = make_float4(acc[0]+la.x, acc[1]+la.y, acc[2]+la.z, acc[3]+la.w);
    *(float4*)(g_y1 + b + 4) = make_float4(acc[4]+lb.x, acc[5]+lb.y, acc[6]+lb.z, acc[7]+lb.w);
    float4 sa = __ldg((const float4*)(g_lins + b));
    float4 sb = __ldg((const float4*)(g_lins + b + 4));
    *(float4*)(g_ys + b)     = make_float4(accs[0]+sa.x, accs[1]+sa.y, accs[2]+sa.z, accs[3]+sa.w);
    *(float4*)(g_ys + b + 4) = make_float4(accs[4]+sb.x, accs[5]+sb.y, accs[6]+sb.z, accs[7]+sb.w);
}

// ------------------------ BN batch stats (y1, ys) ----------------------------
__global__ void k_stat1() {
    __shared__ float red[4][8][33];
    int tid = threadIdx.x, lane = tid & 31, warp = tid >> 5;
    float s1 = 0.f, q1 = 0.f, ss = 0.f, qs = 0.f;
    for (int n = blockIdx.x*8 + warp; n < NN; n += gridDim.x*8) {
        float v = g_y1[(size_t)n*C + lane]; s1 += v; q1 += v*v;
        float u = g_ys[(size_t)n*C + lane]; ss += u; qs += u*u;
    }
    red[0][warp][lane] = s1; red[1][warp][lane] = q1;
    red[2][warp][lane] = ss; red[3][warp][lane] = qs;
    __syncthreads();
    if (warp < 4) {
        float t = 0.f;
        #pragma unroll
        for (int w = 0; w < 8; w++) t += red[warp][w][lane];
        atomicAdd(&g_stat[warp*32 + lane], t);
    }
}

__global__ void k_finA(const float* __restrict__ gam1, const float* __restrict__ bet1,
                       const float* __restrict__ gams, const float* __restrict__ bets) {
    int t = threadIdx.x;
    const float invn = 1.f / (float)NN;
    if (t < 32) {
        float m = g_stat[t] * invn;
        float v = g_stat[32 + t] * invn - m*m;
        float sc = gam1[t] * rsqrtf(v + BNE);
        g_bns[t] = sc; g_bns[32 + t] = bet1[t] - m*sc;
    } else if (t < 64) {
        int c = t - 32;
        float m = g_stat[64 + c] * invn;
        float v = g_stat[96 + c] * invn - m*m;
        float sc = gams[c] * rsqrtf(v + BNE);
        g_bns[64 + c] = sc; g_bns[96 + c] = bets[c] - m*sc;
    }
}

// --------- prepB: h1 = elu(BN1(y1)); lin2 = h1@root2 + b2; store h1 ----------
__global__ void k_prepB(const float* __restrict__ root2, const float* __restrict__ b2) {
    __shared__ float W2[C][C];
    __shared__ float hsh[64][36];
    int tid = threadIdx.x;
    for (int idx = tid; idx < C*C; idx += 256)
        W2[idx >> 5][idx & 31] = root2[idx];
    int n0 = blockIdx.x * 64;
    // phase 1: BN + ELU, store h1 (global + smem tile)
    for (int v = tid; v < 512; v += 256) {
        int ln = v >> 3;
        int j4 = (v & 7) * 4;
        int n = n0 + ln;
        float4 h4 = make_float4(0.f, 0.f, 0.f, 0.f);
        if (n < NN) {
            float4 y  = *(const float4*)(g_y1 + (size_t)n*C + j4);
            float4 sc = *(const float4*)(g_bns + j4);
            float4 sh = *(const float4*)(g_bns + 32 + j4);
            float v0 = y.x*sc.x + sh.x, v1 = y.y*sc.y + sh.y;
            float v2 = y.z*sc.z + sh.z, v3 = y.w*sc.w + sh.w;
            h4.x = (v0 > 0.f) ? v0 : expm1f(v0);
            h4.y = (v1 > 0.f) ? v1 : expm1f(v1);
            h4.z = (v2 > 0.f) ? v2 : expm1f(v2);
            h4.w = (v3 > 0.f) ? v3 : expm1f(v3);
            *(float4*)(g_h1 + (size_t)n*C + j4) = h4;
        }
        *(float4*)&hsh[ln][j4] = h4;
    }
    __syncthreads();
    // phase 2: lin2 = h @ root2 + b2
    int ln = tid >> 2;
    int n = n0 + ln;
    int q = (tid & 3) * 8;
    float acc[8];
    {
        float4 ba = __ldg((const float4*)(b2 + q));
        float4 bb = __ldg((const float4*)(b2 + q + 4));
        acc[0]=ba.x; acc[1]=ba.y; acc[2]=ba.z; acc[3]=ba.w;
        acc[4]=bb.x; acc[5]=bb.y; acc[6]=bb.z; acc[7]=bb.w;
    }
    #pragma unroll
    for (int j = 0; j < C; j += 4) {
        float4 hv = *(const float4*)&hsh[ln][j];
        #pragma unroll
        for (int jj = 0; jj < 4; jj++) {
            float s = (&hv.x)[jj];
            float4 wa = *(const float4*)&W2[j + jj][q];
            float4 wb = *(const float4*)&W2[j + jj][q + 4];
            acc[0] += s*wa.x; acc[1] += s*wa.y; acc[2] += s*wa.z; acc[3] += s*wa.w;
            acc[4] += s*wb.x; acc[5] += s*wb.y; acc[6] += s*wb.z; acc[7] += s*wb.w;
        }
    }
    if (n < NN) {
        size_t b = (size_t)n * C + q;
        *(float4*)(g_lin2 + b)     = make_float4(acc[0], acc[1], acc[2], acc[3]);
        *(float4*)(g_lin2 + b + 4) = make_float4(acc[4], acc[5], acc[6], acc[7]);
    }
}

// ------------------------ edge pass 2 (conv2 K=5): gather h1 -----------------
__global__ void k_edge2() {
    int n = blockIdx.x * 8 + (threadIdx.x >> 5);
    if (n >= NN) return;
    int lane = threadIdx.x & 31;
    int beg = g_ptr[n], end = g_ptr[n + 1];
    float a0 = 0.f, a1 = 0.f, a2 = 0.f, a3 = 0.f, a4 = 0.f;
    int j = beg;
    for (; j + 4 <= end; j += 4) {
        float4 ma[4], mb[4];
        #pragma unroll
        for (int u = 0; u < 4; u++) {
            ma[u] = __ldg(&g_m2[2*(size_t)(j + u)]);
            mb[u] = __ldg(&g_m2[2*(size_t)(j + u) + 1]);
        }
        float hv[4];
        #pragma unroll
        for (int u = 0; u < 4; u++)
            hv[u] = __ldg(&g_h1[(size_t)__float_as_int(ma[u].x)*C + lane]);
        #pragma unroll
        for (int u = 0; u < 4; u++) {
            a0 += ma[u].y * hv[u]; a1 += ma[u].z * hv[u]; a2 += ma[u].w * hv[u];
            a3 += mb[u].x * hv[u]; a4 += mb[u].y * hv[u];
        }
    }
    for (; j < end; j++) {
        float4 ma = __ldg(&g_m2[2*(size_t)j]);
        float4 mb = __ldg(&g_m2[2*(size_t)j + 1]);
        float hv = __ldg(&g_h1[(size_t)__float_as_int(ma.x)*C + lane]);
        a0 += ma.y * hv; a1 += ma.z * hv; a2 += ma.w * hv;
        a3 += mb.x * hv; a4 += mb.y * hv;
    }
    float inv = 1.f / fmaxf((float)(end - beg), 1.f);
    size_t b = (size_t)n * L1 + lane;
    g_z2[b]       = a0 * inv;
    g_z2[b + 32]  = a1 * inv;
    g_z2[b + 64]  = a2 * inv;
    g_z2[b + 96]  = a3 * inv;
    g_z2[b + 128] = a4 * inv;
}

// ---------------------- postB: y2 = z2 @ B2 + lin2 ---------------------------
__global__ void k_postB(const float* __restrict__ g2) {
    __shared__ float B2[L1][C];
    int tid = threadIdx.x;
    for (int idx = tid; idx < C*L1; idx += 256) {
        int i = idx / L1, r = idx % L1;
        int k = r >> 5, c = r & 31;
        B2[k*32 + i][c] = g2[idx];
    }
    __syncthreads();
    int n = blockIdx.x * 64 + (tid >> 2);
    if (n >= NN) return;
    int q = (tid & 3) * 8;
    float acc[8] = {0,0,0,0,0,0,0,0};
    const float* zr = g_z2 + (size_t)n * L1;
    #pragma unroll
    for (int j = 0; j < L1; j += 4) {
        float4 zv = __ldg((const float4*)(zr + j));
        #pragma unroll
        for (int jj = 0; jj < 4; jj++) {
            float s = (&zv.x)[jj];
            float4 wa = *(const float4*)&B2[j + jj][q];
            float4 wb = *(const float4*)&B2[j + jj][q + 4];
            acc[0] += s*wa.x; acc[1] += s*wa.y; acc[2] += s*wa.z; acc[3] += s*wa.w;
            acc[4] += s*wb.x; acc[5] += s*wb.y; acc[6] += s*wb.z; acc[7] += s*wb.w;
        }
    }
    size_t b = (size_t)n * C + q;
    float4 la = __ldg((const float4*)(g_lin2 + b));
    float4 lb = __ldg((const float4*)(g_lin2 + b + 4));
    *(float4*)(g_y2 + b)     = make_float4(acc[0]+la.x, acc[1]+la.y, acc[2]+la.z, acc[3]+la.w);
    *(float4*)(g_y2 + b + 4) = make_float4(acc[4]+lb.x, acc[5]+lb.y, acc[6]+lb.z, acc[7]+lb.w);
}

__global__ void k_stat2() {
    __shared__ float red[2][8][33];
    int tid = threadIdx.x, lane = tid & 31, warp = tid >> 5;
    float s2 = 0.f, q2 = 0.f;
    for (int n = blockIdx.x*8 + warp; n < NN; n += gridDim.x*8) {
        float v = g_y2[(size_t)n*C + lane]; s2 += v; q2 += v*v;
    }
    red[0][warp][lane] = s2; red[1][warp][lane] = q2;
    __syncthreads();
    if (warp < 2) {
        float t = 0.f;
        #pragma unroll
        for (int w = 0; w < 8; w++) t += red[warp][w][lane];
        atomicAdd(&g_stat[128 + warp*32 + lane], t);
    }
}

__global__ void k_finB(const float* __restrict__ gam2, const float* __restrict__ bet2) {
    int t = threadIdx.x;
    if (t < 32) {
        const float invn = 1.f / (float)NN;
        float m = g_stat[128 + t] * invn;
        float v = g_stat[160 + t] * invn - m*m;
        float sc = gam2[t] * rsqrtf(v + BNE);
        g_bns[128 + t] = sc; g_bns[160 + t] = bet2[t] - m*sc;
    }
}

// ------------------- final: out = elu(BN2(y2) + BNs(ys)) ---------------------
__global__ void k_final(float* __restrict__ out) {
    int i = blockIdx.x * 256 + threadIdx.x;
    if (i >= NN*C) return;
    int c = i & 31;
    float v2 = g_y2[i] * g_bns[128 + c] + g_bns[160 + c];
    float vs = g_ys[i] * g_bns[64 + c]  + g_bns[96 + c];
    float h = v2 + vs;
    out[i] = (h > 0.f) ? h : expm1f(h);
}

// ------------------------------------------------------------------------------
extern "C" void kernel_launch(void* const* d_in, const int* in_sizes, int n_in,
                              void* d_out, int out_size) {
    (void)in_sizes; (void)n_in; (void)out_size;
    const float* x     = (const float*)d_in[0];
    const int*   ei    = (const int*)  d_in[1];
    const float* attr  = (const float*)d_in[2];
    const float* g1    = (const float*)d_in[3];
    const float* mu1   = (const float*)d_in[4];
    const float* sg1   = (const float*)d_in[5];
    const float* root1 = (const float*)d_in[6];
    const float* b1    = (const float*)d_in[7];
    const float* gam1  = (const float*)d_in[8];
    const float* bet1  = (const float*)d_in[9];
    const float* g2    = (const float*)d_in[10];
    const float* mu2   = (const float*)d_in[11];
    const float* sg2   = (const float*)d_in[12];
    const float* root2 = (const float*)d_in[13];
    const float* b2    = (const float*)d_in[14];
    const float* gam2  = (const float*)d_in[15];
    const float* bet2  = (const float*)d_in[16];
    const float* gs    = (const float*)d_in[17];
    const float* mus   = (const float*)d_in[18];
    const float* sgs   = (const float*)d_in[19];
    const float* roots = (const float*)d_in[20];
    const float* bs    = (const float*)d_in[21];
    const float* gams  = (const float*)d_in[22];
    const float* bets  = (const float*)d_in[23];
    float* out = (float*)d_out;

    const int nb_scan = (NN + 1023) / 1024;

    k_zero <<<(NN + 255)/256, 256>>>();
    k_prepA<<<(NN + 63)/64,   256>>>(x, root1, b1, roots, bs);
    k_count<<<(EE + 255)/256, 256>>>(ei);
    k_scan1<<<nb_scan, 1024>>>();
    k_scan2<<<1, 32>>>(nb_scan);
    k_scan3<<<(NN + 255)/256, 256>>>();
    k_fill <<<(EE + 255)/256, 256>>>(ei, attr, mu1, sg1, mu2, sg2, mus, sgs);
    k_edge1<<<(NN + 7)/8,     256>>>(x);
    k_postA<<<(NN + 63)/64,   256>>>(g1, gs);
    k_stat1<<<240, 256>>>();
    k_finA <<<1, 64>>>(gam1, bet1, gams, bets);
    k_prepB<<<(NN + 63)/64,   256>>>(root2, b2);
    k_edge2<<<(NN + 7)/8,     256>>>();
    k_postB<<<(NN + 63)/64,   256>>>(g2);
    k_stat2<<<240, 256>>>();
    k_finB <<<1, 32>>>(gam2, bet2);
    k_final<<<(NN*C + 255)/256, 256>>>(out);
}

// round 5
// speedup vs baseline: 1.4326x; 1.1366x over previous
#include <cuda_runtime.h>
#include <cuda_fp16.h>
#include <math.h>

#define NN   100000
#define EE   1600000
#define C    32
#define KK   5
#define L1   (KK*C)          // 160
#define EPSV 1e-15f
#define BNE  1e-5f

// ------------------------- device scratch (no allocs) -------------------------
__device__ float  g_lin1[(size_t)NN*C];
__device__ float  g_lins[(size_t)NN*C];
__device__ float  g_lin2[(size_t)NN*C];
__device__ float  g_z1 [(size_t)NN*L1];
__device__ float  g_zs [(size_t)NN*C];
__device__ float  g_z2 [(size_t)NN*L1];
__device__ float  g_y1 [(size_t)NN*C];
__device__ float  g_ys [(size_t)NN*C];
__device__ float  g_y2 [(size_t)NN*C];
__device__ float  g_h1 [(size_t)NN*C];
__device__ int    g_cnt[NN];
__device__ int    g_ptr[NN+1];
__device__ int    g_pos[NN];
__device__ int    g_bsum[128];
__device__ float  g_stat[8*C];     // [sum_y1, sq_y1, sum_ys, sq_ys, sum_y2, sq_y2, -, -]
__device__ float  g_bns[6*C];      // [sc1, sh1, scs, shs, sc2, sh2]
__device__ float4 g_gpar[22];      // 11 gaussian comps: {mu0,mu1,mu2,_},{i0,i1,i2,_}
// per-CSR-edge compressed meta, 16B each:
//   m1: {src:int, half2(w1_0,w1_1), half2(w1_2,w1_3), half2(w1_4, ws)}
//   m2: {src:int, half2(w2_0,w2_1), half2(w2_2,w2_3), half2(w2_4, 0)}
__device__ uint4  g_m1[(size_t)EE];
__device__ uint4  g_m2[(size_t)EE];

__device__ __forceinline__ float2 h2f(unsigned int u) {
    __half2 h = *reinterpret_cast<__half2*>(&u);
    return __half22float2(h);
}
__device__ __forceinline__ unsigned int f2h(float a, float b) {
    __half2 h = __floats2half2_rn(a, b);
    return *reinterpret_cast<unsigned int*>(&h);
}

// ------------------------------- zero scratch --------------------------------
__global__ void k_zero() {
    int i = blockIdx.x * blockDim.x + threadIdx.x;
    if (i < NN)   g_cnt[i] = 0;
    if (i < 8*C)  g_stat[i] = 0.f;
}

// ---- gaussian param prep: 11 components (conv1 k0-4, conv2 k0-4, shortcut) --
__global__ void k_gprep(const float* __restrict__ mu1, const float* __restrict__ sg1,
                        const float* __restrict__ mu2, const float* __restrict__ sg2,
                        const float* __restrict__ mus, const float* __restrict__ sgs) {
    int t = threadIdx.x;
    if (t >= 11) return;
    const float* mu; const float* sg; int k;
    if (t < 5)       { mu = mu1; sg = sg1; k = t; }
    else if (t < 10) { mu = mu2; sg = sg2; k = t - 5; }
    else             { mu = mus; sg = sgs; k = 0; }
    float m0 = mu[3*k], m1 = mu[3*k+1], m2 = mu[3*k+2];
    float s0 = sg[3*k], s1 = sg[3*k+1], s2 = sg[3*k+2];
    g_gpar[2*t]     = make_float4(m0, m1, m2, 0.f);
    g_gpar[2*t + 1] = make_float4(1.f/(EPSV + s0*s0), 1.f/(EPSV + s1*s1), 1.f/(EPSV + s2*s2), 0.f);
}

// --------------------- prepA: lin1 = x@root1+b1, lins = x@roots+bs -----------
__global__ void k_prepA(const float* __restrict__ x, const float* __restrict__ root1,
                        const float* __restrict__ b1, const float* __restrict__ roots,
                        const float* __restrict__ bs) {
    __shared__ float W1[C][C];
    __shared__ float Ws[C][C];
    int tid = threadIdx.x;
    for (int idx = tid; idx < C*C; idx += 256) {
        W1[idx >> 5][idx & 31] = root1[idx];
        Ws[idx >> 5][idx & 31] = roots[idx];
    }
    __syncthreads();
    int n = blockIdx.x * 64 + (tid >> 2);
    if (n >= NN) return;
    int q = (tid & 3) * 8;
    float a1_[8], as_[8];
    {
        float4 ba = __ldg((const float4*)(b1 + q));
        float4 bb = __ldg((const float4*)(b1 + q + 4));
        a1_[0]=ba.x; a1_[1]=ba.y; a1_[2]=ba.z; a1_[3]=ba.w;
        a1_[4]=bb.x; a1_[5]=bb.y; a1_[6]=bb.z; a1_[7]=bb.w;
        float4 ca = __ldg((const float4*)(bs + q));
        float4 cb = __ldg((const float4*)(bs + q + 4));
        as_[0]=ca.x; as_[1]=ca.y; as_[2]=ca.z; as_[3]=ca.w;
        as_[4]=cb.x; as_[5]=cb.y; as_[6]=cb.z; as_[7]=cb.w;
    }
    const float* xr = x + (size_t)n * C;
    #pragma unroll
    for (int j = 0; j < C; j += 4) {
        float4 xv = __ldg((const float4*)(xr + j));
        #pragma unroll
        for (int jj = 0; jj < 4; jj++) {
            float s = (&xv.x)[jj];
            float4 wa = *(const float4*)&W1[j + jj][q];
            float4 wb = *(const float4*)&W1[j + jj][q + 4];
            a1_[0] += s*wa.x; a1_[1] += s*wa.y; a1_[2] += s*wa.z; a1_[3] += s*wa.w;
            a1_[4] += s*wb.x; a1_[5] += s*wb.y; a1_[6] += s*wb.z; a1_[7] += s*wb.w;
            float4 va = *(const float4*)&Ws[j + jj][q];
            float4 vb = *(const float4*)&Ws[j + jj][q + 4];
            as_[0] += s*va.x; as_[1] += s*va.y; as_[2] += s*va.z; as_[3] += s*va.w;
            as_[4] += s*vb.x; as_[5] += s*vb.y; as_[6] += s*vb.z; as_[7] += s*vb.w;
        }
    }
    size_t b = (size_t)n * C + q;
    *(float4*)(g_lin1 + b)     = make_float4(a1_[0], a1_[1], a1_[2], a1_[3]);
    *(float4*)(g_lin1 + b + 4) = make_float4(a1_[4], a1_[5], a1_[6], a1_[7]);
    *(float4*)(g_lins + b)     = make_float4(as_[0], as_[1], as_[2], as_[3]);
    *(float4*)(g_lins + b + 4) = make_float4(as_[4], as_[5], as_[6], as_[7]);
}

// ------------------------------ CSR build ------------------------------------
__global__ void k_count(const int* __restrict__ ei) {
    int e = blockIdx.x * 256 + threadIdx.x;
    if (e < EE) atomicAdd(&g_cnt[ei[EE + e]], 1);
}

__global__ void k_scan1() {
    __shared__ int sd[1024];
    int tid = threadIdx.x;
    int i = blockIdx.x * 1024 + tid;
    int v = (i < NN) ? g_cnt[i] : 0;
    sd[tid] = v; __syncthreads();
    for (int off = 1; off < 1024; off <<= 1) {
        int t = (tid >= off) ? sd[tid - off] : 0;
        __syncthreads();
        sd[tid] += t; __syncthreads();
    }
    if (i < NN) g_ptr[i] = sd[tid] - v;           // block-local exclusive
    if (tid == 1023) g_bsum[blockIdx.x] = sd[1023];
}

__global__ void k_scan2(int nb) {
    if (threadIdx.x == 0) {
        int run = 0;
        for (int b = 0; b < nb; b++) { int t = g_bsum[b]; g_bsum[b] = run; run += t; }
    }
}

__global__ void k_scan3() {
    int i = blockIdx.x * 256 + threadIdx.x;
    if (i < NN) {
        int p = g_ptr[i] + g_bsum[i >> 10];
        g_ptr[i] = p; g_pos[i] = p;
    }
    if (i == 0) g_ptr[NN] = EE;
}

// ---- fill: scatter edges into CSR; gaussian weights from hoisted params -----
__global__ void k_fill(const int* __restrict__ ei, const float* __restrict__ attr) {
    int e = blockIdx.x * 256 + threadIdx.x;
    if (e >= EE) return;
    int s = ei[e], d = ei[EE + e];
    float a0 = attr[3*e], a1 = attr[3*e + 1], a2 = attr[3*e + 2];
    float w[11];
    #pragma unroll
    for (int t = 0; t < 11; t++) {
        float4 mu = __ldg(&g_gpar[2*t]);
        float4 iv = __ldg(&g_gpar[2*t + 1]);
        float d0 = a0 - mu.x, d1 = a1 - mu.y, d2 = a2 - mu.z;
        w[t] = __expf(-0.5f * (d0*d0*iv.x + d1*d1*iv.y + d2*d2*iv.z));
    }
    int p = atomicAdd(&g_pos[d], 1);
    uint4 v1, v2;
    v1.x = (unsigned int)s;  v1.y = f2h(w[0], w[1]); v1.z = f2h(w[2], w[3]); v1.w = f2h(w[4], w[10]);
    v2.x = (unsigned int)s;  v2.y = f2h(w[5], w[6]); v2.z = f2h(w[7], w[8]); v2.w = f2h(w[9], 0.f);
    g_m1[p] = v1;
    g_m2[p] = v2;
}

// ------------- edge pass 1 (conv1 K=5 + shortcut K=1, fused): gather x -------
// unroll-8, one LDG.128 meta + one gather per edge, MLP ~16
__global__ void k_edge1(const float* __restrict__ x) {
    int n = blockIdx.x * 8 + (threadIdx.x >> 5);
    if (n >= NN) return;
    int lane = threadIdx.x & 31;
    int beg = __ldg(&g_ptr[n]), end = __ldg(&g_ptr[n + 1]);
    float a0 = 0.f, a1 = 0.f, a2 = 0.f, a3 = 0.f, a4 = 0.f, aS = 0.f;
    int j = beg;
    for (; j + 8 <= end; j += 8) {
        uint4 m[8];
        #pragma unroll
        for (int u = 0; u < 8; u++) m[u] = __ldg(&g_m1[(size_t)(j + u)]);
        float xv[8];
        #pragma unroll
        for (int u = 0; u < 8; u++)
            xv[u] = __ldg(x + (size_t)(int)m[u].x * C + lane);
        #pragma unroll
        for (int u = 0; u < 8; u++) {
            float2 w01 = h2f(m[u].y), w23 = h2f(m[u].z), w4s = h2f(m[u].w);
            a0 += w01.x * xv[u]; a1 += w01.y * xv[u];
            a2 += w23.x * xv[u]; a3 += w23.y * xv[u];
            a4 += w4s.x * xv[u]; aS += w4s.y * xv[u];
        }
    }
    for (; j < end; j++) {
        uint4 m = __ldg(&g_m1[(size_t)j]);
        float xv = __ldg(x + (size_t)(int)m.x * C + lane);
        float2 w01 = h2f(m.y), w23 = h2f(m.z), w4s = h2f(m.w);
        a0 += w01.x * xv; a1 += w01.y * xv;
        a2 += w23.x * xv; a3 += w23.y * xv;
        a4 += w4s.x * xv; aS += w4s.y * xv;
    }
    float inv = 1.f / fmaxf((float)(end - beg), 1.f);
    size_t b = (size_t)n * L1 + lane;
    g_z1[b]       = a0 * inv;
    g_z1[b + 32]  = a1 * inv;
    g_z1[b + 64]  = a2 * inv;
    g_z1[b + 96]  = a3 * inv;
    g_z1[b + 128] = a4 * inv;
    g_zs[(size_t)n*C + lane] = aS * inv;
}

// -------- postA: y1 = z1 @ B1 + lin1 ; ys = zs @ gs + lins -------------------
__global__ void k_postA(const float* __restrict__ g1, const float* __restrict__ gs) {
    __shared__ float B1[L1][C];      // B1[k*32+i][o] = g1[i][k*32+o]
    __shared__ float Bs[C][C];
    int tid = threadIdx.x;
    for (int idx = tid; idx < C*L1; idx += 256) {
        int i = idx / L1, r = idx % L1;
        int k = r >> 5, c = r & 31;
        B1[k*32 + i][c] = g1[idx];
    }
    for (int idx = tid; idx < C*C; idx += 256)
        Bs[idx >> 5][idx & 31] = gs[idx];
    __syncthreads();
    int n = blockIdx.x * 64 + (tid >> 2);
    if (n >= NN) return;
    int q = (tid & 3) * 8;
    float acc[8] = {0,0,0,0,0,0,0,0};
    const float* zr = g_z1 + (size_t)n * L1;
    #pragma unroll
    for (int j = 0; j < L1; j += 4) {
        float4 zv = __ldg((const float4*)(zr + j));
        #pragma unroll
        for (int jj = 0; jj < 4; jj++) {
            float s = (&zv.x)[jj];
            float4 wa = *(const float4*)&B1[j + jj][q];
            float4 wb = *(const float4*)&B1[j + jj][q + 4];
            acc[0] += s*wa.x; acc[1] += s*wa.y; acc[2] += s*wa.z; acc[3] += s*wa.w;
            acc[4] += s*wb.x; acc[5] += s*wb.y; acc[6] += s*wb.z; acc[7] += s*wb.w;
        }
    }
    float accs[8] = {0,0,0,0,0,0,0,0};
    const float* zsr = g_zs + (size_t)n * C;
    #pragma unroll
    for (int j = 0; j < C; j += 4) {
        float4 zv = __ldg((const float4*)(zsr + j));
        #pragma unroll
        for (int jj = 0; jj < 4; jj++) {
            float s = (&zv.x)[jj];
            float4 wa = *(const float4*)&Bs[j + jj][q];
            float4 wb = *(const float4*)&Bs[j + jj][q + 4];
            accs[0] += s*wa.x; accs[1] += s*wa.y; accs[2] += s*wa.z; accs[3] += s*wa.w;
            accs[4] += s*wb.x; accs[5] += s*wb.y; accs[6] += s*wb.z; accs[7] += s*wb.w;
        }
    }
    size_t b = (size_t)n * C + q;
    float4 la = __ldg((const float4*)(g_lin1 + b));
    float4 lb = __ldg((const float4*)(g_lin1 + b + 4));
    *(float4*)(g_y1 + b)     = make_float4(acc[0]+la.x, acc[1]+la.y, acc[2]+la.z, acc[3]+la.w);
    *(float4*)(g_y1 + b + 4) = make_float4(acc[4]+lb.x, acc[5]+lb.y, acc[6]+lb.z, acc[7]+lb.w);
    float4 sa = __ldg((const float4*)(g_lins + b));
    float4 sb = __ldg((const float4*)(g_lins + b + 4));
    *(float4*)(g_ys + b)     = make_float4(accs[0]+sa.x, accs[1]+sa.y, accs[2]+sa.z, accs[3]+sa.w);
    *(float4*)(g_ys + b + 4) = make_float4(accs[4]+sb.x, accs[5]+sb.y, accs[6]+sb.z, accs[7]+sb.w);
}

// ------------------------ BN batch stats (y1, ys) ----------------------------
__global__ void k_stat1() {
    __shared__ float red[4][8][33];
    int tid = threadIdx.x, lane = tid & 31, warp = tid >> 5;
    float s1 = 0.f, q1 = 0.f, ss = 0.f, qs = 0.f;
    for (int n = blockIdx.x*8 + warp; n < NN; n += gridDim.x*8) {
        float v = g_y1[(size_t)n*C + lane]; s1 += v; q1 += v*v;
        float u = g_ys[(size_t)n*C + lane]; ss += u; qs += u*u;
    }
    red[0][warp][lane] = s1; red[1][warp][lane] = q1;
    red[2][warp][lane] = ss; red[3][warp][lane] = qs;
    __syncthreads();
    if (warp < 4) {
        float t = 0.f;
        #pragma unroll
        for (int w = 0; w < 8; w++) t += red[warp][w][lane];
        atomicAdd(&g_stat[warp*32 + lane], t);
    }
}

__global__ void k_finA(const float* __restrict__ gam1, const float* __restrict__ bet1,
                       const float* __restrict__ gams, const float* __restrict__ bets) {
    int t = threadIdx.x;
    const float invn = 1.f / (float)NN;
    if (t < 32) {
        float m = g_stat[t] * invn;
        float v = g_stat[32 + t] * invn - m*m;
        float sc = gam1[t] * rsqrtf(v + BNE);
        g_bns[t] = sc; g_bns[32 + t] = bet1[t] - m*sc;
    } else if (t < 64) {
        int c = t - 32;
        float m = g_stat[64 + c] * invn;
        float v = g_stat[96 + c] * invn - m*m;
        float sc = gams[c] * rsqrtf(v + BNE);
        g_bns[64 + c] = sc; g_bns[96 + c] = bets[c] - m*sc;
    }
}

// --------- prepB: h1 = elu(BN1(y1)); lin2 = h1@root2 + b2; store h1 ----------
__global__ void k_prepB(const float* __restrict__ root2, const float* __restrict__ b2) {
    __shared__ float W2[C][C];
    __shared__ float hsh[64][36];
    int tid = threadIdx.x;
    for (int idx = tid; idx < C*C; idx += 256)
        W2[idx >> 5][idx & 31] = root2[idx];
    int n0 = blockIdx.x * 64;
    for (int v = tid; v < 512; v += 256) {
        int ln = v >> 3;
        int j4 = (v & 7) * 4;
        int n = n0 + ln;
        float4 h4 = make_float4(0.f, 0.f, 0.f, 0.f);
        if (n < NN) {
            float4 y  = *(const float4*)(g_y1 + (size_t)n*C + j4);
            float4 sc = *(const float4*)(g_bns + j4);
            float4 sh = *(const float4*)(g_bns + 32 + j4);
            float v0 = y.x*sc.x + sh.x, v1 = y.y*sc.y + sh.y;
            float v2 = y.z*sc.z + sh.z, v3 = y.w*sc.w + sh.w;
            h4.x = (v0 > 0.f) ? v0 : expm1f(v0);
            h4.y = (v1 > 0.f) ? v1 : expm1f(v1);
            h4.z = (v2 > 0.f) ? v2 : expm1f(v2);
            h4.w = (v3 > 0.f) ? v3 : expm1f(v3);
            *(float4*)(g_h1 + (size_t)n*C + j4) = h4;
        }
        *(float4*)&hsh[ln][j4] = h4;
    }
    __syncthreads();
    int ln = tid >> 2;
    int n = n0 + ln;
    int q = (tid & 3) * 8;
    float acc[8];
    {
        float4 ba = __ldg((const float4*)(b2 + q));
        float4 bb = __ldg((const float4*)(b2 + q + 4));
        acc[0]=ba.x; acc[1]=ba.y; acc[2]=ba.z; acc[3]=ba.w;
        acc[4]=bb.x; acc[5]=bb.y; acc[6]=bb.z; acc[7]=bb.w;
    }
    #pragma unroll
    for (int j = 0; j < C; j += 4) {
        float4 hv = *(const float4*)&hsh[ln][j];
        #pragma unroll
        for (int jj = 0; jj < 4; jj++) {
            float s = (&hv.x)[jj];
            float4 wa = *(const float4*)&W2[j + jj][q];
            float4 wb = *(const float4*)&W2[j + jj][q + 4];
            acc[0] += s*wa.x; acc[1] += s*wa.y; acc[2] += s*wa.z; acc[3] += s*wa.w;
            acc[4] += s*wb.x; acc[5] += s*wb.y; acc[6] += s*wb.z; acc[7] += s*wb.w;
        }
    }
    if (n < NN) {
        size_t b = (size_t)n * C + q;
        *(float4*)(g_lin2 + b)     = make_float4(acc[0], acc[1], acc[2], acc[3]);
        *(float4*)(g_lin2 + b + 4) = make_float4(acc[4], acc[5], acc[6], acc[7]);
    }
}

// ------------------------ edge pass 2 (conv2 K=5): gather h1 -----------------
__global__ void k_edge2() {
    int n = blockIdx.x * 8 + (threadIdx.x >> 5);
    if (n >= NN) return;
    int lane = threadIdx.x & 31;
    int beg = __ldg(&g_ptr[n]), end = __ldg(&g_ptr[n + 1]);
    float a0 = 0.f, a1 = 0.f, a2 = 0.f, a3 = 0.f, a4 = 0.f;
    int j = beg;
    for (; j + 8 <= end; j += 8) {
        uint4 m[8];
        #pragma unroll
        for (int u = 0; u < 8; u++) m[u] = __ldg(&g_m2[(size_t)(j + u)]);
        float hv[8];
        #pragma unroll
        for (int u = 0; u < 8; u++)
            hv[u] = __ldg(&g_h1[(size_t)(int)m[u].x * C + lane]);
        #pragma unroll
        for (int u = 0; u < 8; u++) {
            float2 w01 = h2f(m[u].y), w23 = h2f(m[u].z), w4x = h2f(m[u].w);
            a0 += w01.x * hv[u]; a1 += w01.y * hv[u];
            a2 += w23.x * hv[u]; a3 += w23.y * hv[u];
            a4 += w4x.x * hv[u];
        }
    }
    for (; j < end; j++) {
        uint4 m = __ldg(&g_m2[(size_t)j]);
        float hv = __ldg(&g_h1[(size_t)(int)m.x * C + lane]);
        float2 w01 = h2f(m.y), w23 = h2f(m.z), w4x = h2f(m.w);
        a0 += w01.x * hv; a1 += w01.y * hv;
        a2 += w23.x * hv; a3 += w23.y * hv;
        a4 += w4x.x * hv;
    }
    float inv = 1.f / fmaxf((float)(end - beg), 1.f);
    size_t b = (size_t)n * L1 + lane;
    g_z2[b]       = a0 * inv;
    g_z2[b + 32]  = a1 * inv;
    g_z2[b + 64]  = a2 * inv;
    g_z2[b + 96]  = a3 * inv;
    g_z2[b + 128] = a4 * inv;
}

// ---------------------- postB: y2 = z2 @ B2 + lin2 ---------------------------
__global__ void k_postB(const float* __restrict__ g2) {
    __shared__ float B2[L1][C];
    int tid = threadIdx.x;
    for (int idx = tid; idx < C*L1; idx += 256) {
        int i = idx / L1, r = idx % L1;
        int k = r >> 5, c = r & 31;
        B2[k*32 + i][c] = g2[idx];
    }
    __syncthreads();
    int n = blockIdx.x * 64 + (tid >> 2);
    if (n >= NN) return;
    int q = (tid & 3) * 8;
    float acc[8] = {0,0,0,0,0,0,0,0};
    const float* zr = g_z2 + (size_t)n * L1;
    #pragma unroll
    for (int j = 0; j < L1; j += 4) {
        float4 zv = __ldg((const float4*)(zr + j));
        #pragma unroll
        for (int jj = 0; jj < 4; jj++) {
            float s = (&zv.x)[jj];
            float4 wa = *(const float4*)&B2[j + jj][q];
            float4 wb = *(const float4*)&B2[j + jj][q + 4];
            acc[0] += s*wa.x; acc[1] += s*wa.y; acc[2] += s*wa.z; acc[3] += s*wa.w;
            acc[4] += s*wb.x; acc[5] += s*wb.y; acc[6] += s*wb.z; acc[7] += s*wb.w;
        }
    }
    size_t b = (size_t)n * C + q;
    float4 la = __ldg((const float4*)(g_lin2 + b));
    float4 lb = __ldg((const float4*)(g_lin2 + b + 4));
    *(float4*)(g_y2 + b)     = make_float4(acc[0]+la.x, acc[1]+la.y, acc[2]+la.z, acc[3]+la.w);
    *(float4*)(g_y2 + b + 4) = make_float4(acc[4]+lb.x, acc[5]+lb.y, acc[6]+lb.z, acc[7]+lb.w);
}

__global__ void k_stat2() {
    __shared__ float red[2][8][33];
    int tid = threadIdx.x, lane = tid & 31, warp = tid >> 5;
    float s2 = 0.f, q2 = 0.f;
    for (int n = blockIdx.x*8 + warp; n < NN; n += gridDim.x*8) {
        float v = g_y2[(size_t)n*C + lane]; s2 += v; q2 += v*v;
    }
    red[0][warp][lane] = s2; red[1][warp][lane] = q2;
    __syncthreads();
    if (warp < 2) {
        float t = 0.f;
        #pragma unroll
        for (int w = 0; w < 8; w++) t += red[warp][w][lane];
        atomicAdd(&g_stat[128 + warp*32 + lane], t);
    }
}

__global__ void k_finB(const float* __restrict__ gam2, const float* __restrict__ bet2) {
    int t = threadIdx.x;
    if (t < 32) {
        const float invn = 1.f / (float)NN;
        float m = g_stat[128 + t] * invn;
        float v = g_stat[160 + t] * invn - m*m;
        float sc = gam2[t] * rsqrtf(v + BNE);
        g_bns[128 + t] = sc; g_bns[160 + t] = bet2[t] - m*sc;
    }
}

// ------------------- final: out = elu(BN2(y2) + BNs(ys)) ---------------------
__global__ void k_final(float* __restrict__ out) {
    int i = blockIdx.x * 256 + threadIdx.x;
    if (i >= NN*C) return;
    int c = i & 31;
    float v2 = g_y2[i] * g_bns[128 + c] + g_bns[160 + c];
    float vs = g_ys[i] * g_bns[64 + c]  + g_bns[96 + c];
    float h = v2 + vs;
    out[i] = (h > 0.f) ? h : expm1f(h);
}

// ------------------------------------------------------------------------------
extern "C" void kernel_launch(void* const* d_in, const int* in_sizes, int n_in,
                              void* d_out, int out_size) {
    (void)in_sizes; (void)n_in; (void)out_size;
    const float* x     = (const float*)d_in[0];
    const int*   ei    = (const int*)  d_in[1];
    const float* attr  = (const float*)d_in[2];
    const float* g1    = (const float*)d_in[3];
    const float* mu1   = (const float*)d_in[4];
    const float* sg1   = (const float*)d_in[5];
    const float* root1 = (const float*)d_in[6];
    const float* b1    = (const float*)d_in[7];
    const float* gam1  = (const float*)d_in[8];
    const float* bet1  = (const float*)d_in[9];
    const float* g2    = (const float*)d_in[10];
    const float* mu2   = (const float*)d_in[11];
    const float* sg2   = (const float*)d_in[12];
    const float* root2 = (const float*)d_in[13];
    const float* b2    = (const float*)d_in[14];
    const float* gam2  = (const float*)d_in[15];
    const float* bet2  = (const float*)d_in[16];
    const float* gs    = (const float*)d_in[17];
    const float* mus   = (const float*)d_in[18];
    const float* sgs   = (const float*)d_in[19];
    const float* roots = (const float*)d_in[20];
    const float* bs    = (const float*)d_in[21];
    const float* gams  = (const float*)d_in[22];
    const float* bets  = (const float*)d_in[23];
    float* out = (float*)d_out;

    const int nb_scan = (NN + 1023) / 1024;

    k_zero <<<(NN + 255)/256, 256>>>();
    k_gprep<<<1, 32>>>(mu1, sg1, mu2, sg2, mus, sgs);
    k_prepA<<<(NN + 63)/64,   256>>>(x, root1, b1, roots, bs);
    k_count<<<(EE + 255)/256, 256>>>(ei);
    k_scan1<<<nb_scan, 1024>>>();
    k_scan2<<<1, 32>>>(nb_scan);
    k_scan3<<<(NN + 255)/256, 256>>>();
    k_fill <<<(EE + 255)/256, 256>>>(ei, attr);
    k_edge1<<<(NN + 7)/8,     256>>>(x);
    k_postA<<<(NN + 63)/64,   256>>>(g1, gs);
    k_stat1<<<240, 256>>>();
    k_finA <<<1, 64>>>(gam1, bet1, gams, bets);
    k_prepB<<<(NN + 63)/64,   256>>>(root2, b2);
    k_edge2<<<(NN + 7)/8,     256>>>();
    k_postB<<<(NN + 63)/64,   256>>>(g2);
    k_stat2<<<240, 256>>>();
    k_finB <<<1, 32>>>(gam2, bet2);
    k_final<<<(NN*C + 255)/256, 256>>>(out);
}

// round 6
// speedup vs baseline: 1.4523x; 1.0137x over previous
#include <cuda_runtime.h>
#include <cuda_fp16.h>
#include <math.h>

#define NN   100000
#define EE   1600000
#define C    32
#define KK   5
#define L1   (KK*C)          // 160
#define EPSV 1e-15f
#define BNE  1e-5f

// ------------------------- device scratch (no allocs) -------------------------
__device__ float  g_z1 [(size_t)NN*L1];
__device__ float  g_zs [(size_t)NN*C];
__device__ float  g_z2 [(size_t)NN*L1];
__device__ float  g_y1 [(size_t)NN*C];
__device__ float  g_ys [(size_t)NN*C];
__device__ float  g_y2 [(size_t)NN*C];
__device__ float  g_h1 [(size_t)NN*C];
__device__ int    g_cnt[NN];
__device__ int    g_ptr[NN+1];
__device__ int    g_pos[NN];
__device__ int    g_bsum[128];
__device__ float  g_stat[8*C];     // [sum_y1, sq_y1, sum_ys, sq_ys, sum_y2, sq_y2, -, -]
__device__ float  g_bns[6*C];      // [sc1, sh1, scs, shs, sc2, sh2]
__device__ float4 g_gpar[22];      // 11 gaussian comps: {mu0,mu1,mu2,_},{i0,i1,i2,_}
// per-CSR-edge compressed meta, interleaved 32B (full-sector scatter writes):
//   g_m[2p]   = {src:int, half2(w1_0,w1_1), half2(w1_2,w1_3), half2(w1_4, ws)}
//   g_m[2p+1] = {src:int, half2(w2_0,w2_1), half2(w2_2,w2_3), half2(w2_4, 0)}
__device__ uint4  g_m[(size_t)2*EE];

__device__ __forceinline__ float2 h2f(unsigned int u) {
    __half2 h = *reinterpret_cast<__half2*>(&u);
    return __half22float2(h);
}
__device__ __forceinline__ unsigned int f2h(float a, float b) {
    __half2 h = __floats2half2_rn(a, b);
    return *reinterpret_cast<unsigned int*>(&h);
}

// ------------------- zero scratch + gaussian param prep ----------------------
__global__ void k_zg(const float* __restrict__ mu1, const float* __restrict__ sg1,
                     const float* __restrict__ mu2, const float* __restrict__ sg2,
                     const float* __restrict__ mus, const float* __restrict__ sgs) {
    int i = blockIdx.x * 256 + threadIdx.x;
    if (i < NN)   g_cnt[i] = 0;
    if (i < 8*C)  g_stat[i] = 0.f;
    if (i < 11) {
        const float* mu; const float* sg; int k;
        if (i < 5)       { mu = mu1; sg = sg1; k = i; }
        else if (i < 10) { mu = mu2; sg = sg2; k = i - 5; }
        else             { mu = mus; sg = sgs; k = 0; }
        float m0 = mu[3*k], m1 = mu[3*k+1], m2 = mu[3*k+2];
        float s0 = sg[3*k], s1 = sg[3*k+1], s2 = sg[3*k+2];
        g_gpar[2*i]     = make_float4(m0, m1, m2, 0.f);
        g_gpar[2*i + 1] = make_float4(1.f/(EPSV + s0*s0), 1.f/(EPSV + s1*s1), 1.f/(EPSV + s2*s2), 0.f);
    }
}

// ------------------------------ CSR build ------------------------------------
__global__ void k_count(const int* __restrict__ ei) {
    int e = blockIdx.x * 256 + threadIdx.x;
    if (e < EE) atomicAdd(&g_cnt[ei[EE + e]], 1);
}

__global__ void k_scan1() {
    __shared__ int sd[1024];
    int tid = threadIdx.x;
    int i = blockIdx.x * 1024 + tid;
    int v = (i < NN) ? g_cnt[i] : 0;
    sd[tid] = v; __syncthreads();
    for (int off = 1; off < 1024; off <<= 1) {
        int t = (tid >= off) ? sd[tid - off] : 0;
        __syncthreads();
        sd[tid] += t; __syncthreads();
    }
    if (i < NN) g_ptr[i] = sd[tid] - v;           // block-local exclusive
    if (tid == 1023) g_bsum[blockIdx.x] = sd[1023];
}

// parallel exclusive scan of <=128 block sums in one block
__global__ void k_scan2(int nb) {
    __shared__ int ws[4];
    int t = threadIdx.x;                  // 128 threads
    int lane = t & 31, w = t >> 5;
    int orig = (t < nb) ? g_bsum[t] : 0;
    int v = orig;
    #pragma unroll
    for (int o = 1; o < 32; o <<= 1) {
        int u = __shfl_up_sync(0xffffffffu, v, o);
        if (lane >= o) v += u;
    }
    if (lane == 31) ws[w] = v;
    __syncthreads();
    int add = 0;
    #pragma unroll
    for (int i = 0; i < 4; i++) if (i < w) add += ws[i];
    v += add;
    if (t < nb) g_bsum[t] = v - orig;     // exclusive
}

__global__ void k_scan3() {
    int i = blockIdx.x * 256 + threadIdx.x;
    if (i < NN) {
        int p = g_ptr[i] + g_bsum[i >> 10];
        g_ptr[i] = p; g_pos[i] = p;
    }
    if (i == 0) g_ptr[NN] = EE;
}

// ---- fill: scatter edges into CSR; gaussian weights from hoisted params -----
__global__ void k_fill(const int* __restrict__ ei, const float* __restrict__ attr) {
    int e = blockIdx.x * 256 + threadIdx.x;
    if (e >= EE) return;
    int s = ei[e], d = ei[EE + e];
    float a0 = attr[3*e], a1 = attr[3*e + 1], a2 = attr[3*e + 2];
    float w[11];
    #pragma unroll
    for (int t = 0; t < 11; t++) {
        float4 mu = __ldg(&g_gpar[2*t]);
        float4 iv = __ldg(&g_gpar[2*t + 1]);
        float d0 = a0 - mu.x, d1 = a1 - mu.y, d2 = a2 - mu.z;
        w[t] = __expf(-0.5f * (d0*d0*iv.x + d1*d1*iv.y + d2*d2*iv.z));
    }
    int p = atomicAdd(&g_pos[d], 1);
    uint4 v1, v2;
    v1.x = (unsigned int)s;  v1.y = f2h(w[0], w[1]); v1.z = f2h(w[2], w[3]); v1.w = f2h(w[4], w[10]);
    v2.x = (unsigned int)s;  v2.y = f2h(w[5], w[6]); v2.z = f2h(w[7], w[8]); v2.w = f2h(w[9], 0.f);
    g_m[2*(size_t)p]     = v1;            // full 32B sector per edge
    g_m[2*(size_t)p + 1] = v2;
}

// ------------- edge pass 1 (conv1 K=5 + shortcut K=1, fused): gather x -------
__global__ void k_edge1(const float* __restrict__ x) {
    int n = blockIdx.x * 8 + (threadIdx.x >> 5);
    if (n >= NN) return;
    int lane = threadIdx.x & 31;
    int beg = __ldg(&g_ptr[n]), end = __ldg(&g_ptr[n + 1]);
    float a0 = 0.f, a1 = 0.f, a2 = 0.f, a3 = 0.f, a4 = 0.f, aS = 0.f;
    int j = beg;
    for (; j + 8 <= end; j += 8) {
        uint4 m[8];
        #pragma unroll
        for (int u = 0; u < 8; u++) m[u] = __ldg(&g_m[2*(size_t)(j + u)]);
        float xv[8];
        #pragma unroll
        for (int u = 0; u < 8; u++)
            xv[u] = __ldg(x + (size_t)(int)m[u].x * C + lane);
        #pragma unroll
        for (int u = 0; u < 8; u++) {
            float2 w01 = h2f(m[u].y), w23 = h2f(m[u].z), w4s = h2f(m[u].w);
            a0 += w01.x * xv[u]; a1 += w01.y * xv[u];
            a2 += w23.x * xv[u]; a3 += w23.y * xv[u];
            a4 += w4s.x * xv[u]; aS += w4s.y * xv[u];
        }
    }
    for (; j < end; j++) {
        uint4 m = __ldg(&g_m[2*(size_t)j]);
        float xv = __ldg(x + (size_t)(int)m.x * C + lane);
        float2 w01 = h2f(m.y), w23 = h2f(m.z), w4s = h2f(m.w);
        a0 += w01.x * xv; a1 += w01.y * xv;
        a2 += w23.x * xv; a3 += w23.y * xv;
        a4 += w4s.x * xv; aS += w4s.y * xv;
    }
    float inv = 1.f / fmaxf((float)(end - beg), 1.f);
    size_t b = (size_t)n * L1 + lane;
    g_z1[b]       = a0 * inv;
    g_z1[b + 32]  = a1 * inv;
    g_z1[b + 64]  = a2 * inv;
    g_z1[b + 96]  = a3 * inv;
    g_z1[b + 128] = a4 * inv;
    g_zs[(size_t)n*C + lane] = aS * inv;
}

// -------- postA: y1 = z1@B1 + x@root1 + b1 ; ys = zs@gs + x@roots + bs -------
// + fused BN batch statistics (sum/sumsq of y1, ys)
__global__ void k_postA(const float* __restrict__ x,
                        const float* __restrict__ g1, const float* __restrict__ gs,
                        const float* __restrict__ root1, const float* __restrict__ b1,
                        const float* __restrict__ roots, const float* __restrict__ bs) {
    __shared__ float B1[L1][C];      // B1[k*32+i][o] = g1[i][k*32+o]
    __shared__ float Bs[C][C];
    __shared__ float W1[C][C];
    __shared__ float Ws[C][C];
    __shared__ float red[8][4][C];
    int tid = threadIdx.x;
    for (int idx = tid; idx < C*L1; idx += 256) {
        int i = idx / L1, r = idx % L1;
        B1[(r >> 5)*32 + i][r & 31] = g1[idx];
    }
    for (int idx = tid; idx < C*C; idx += 256) {
        Bs[idx >> 5][idx & 31] = gs[idx];
        W1[idx >> 5][idx & 31] = root1[idx];
        Ws[idx >> 5][idx & 31] = roots[idx];
    }
    __syncthreads();
    int n = blockIdx.x * 64 + (tid >> 2);
    int q = (tid & 3) * 8;
    bool valid = (n < NN);
    float acc[8]  = {0,0,0,0,0,0,0,0};
    float accs[8] = {0,0,0,0,0,0,0,0};
    if (valid) {
        {
            float4 ba = __ldg((const float4*)(b1 + q));
            float4 bb = __ldg((const float4*)(b1 + q + 4));
            acc[0]=ba.x; acc[1]=ba.y; acc[2]=ba.z; acc[3]=ba.w;
            acc[4]=bb.x; acc[5]=bb.y; acc[6]=bb.z; acc[7]=bb.w;
            float4 ca = __ldg((const float4*)(bs + q));
            float4 cb = __ldg((const float4*)(bs + q + 4));
            accs[0]=ca.x; accs[1]=ca.y; accs[2]=ca.z; accs[3]=ca.w;
            accs[4]=cb.x; accs[5]=cb.y; accs[6]=cb.z; accs[7]=cb.w;
        }
        const float* zr = g_z1 + (size_t)n * L1;
        #pragma unroll
        for (int j = 0; j < L1; j += 4) {
            float4 zv = __ldg((const float4*)(zr + j));
            #pragma unroll
            for (int jj = 0; jj < 4; jj++) {
                float s = (&zv.x)[jj];
                float4 wa = *(const float4*)&B1[j + jj][q];
                float4 wb = *(const float4*)&B1[j + jj][q + 4];
                acc[0] += s*wa.x; acc[1] += s*wa.y; acc[2] += s*wa.z; acc[3] += s*wa.w;
                acc[4] += s*wb.x; acc[5] += s*wb.y; acc[6] += s*wb.z; acc[7] += s*wb.w;
            }
        }
        const float* zsr = g_zs + (size_t)n * C;
        #pragma unroll
        for (int j = 0; j < C; j += 4) {
            float4 zv = __ldg((const float4*)(zsr + j));
            #pragma unroll
            for (int jj = 0; jj < 4; jj++) {
                float s = (&zv.x)[jj];
                float4 wa = *(const float4*)&Bs[j + jj][q];
                float4 wb = *(const float4*)&Bs[j + jj][q + 4];
                accs[0] += s*wa.x; accs[1] += s*wa.y; accs[2] += s*wa.z; accs[3] += s*wa.w;
                accs[4] += s*wb.x; accs[5] += s*wb.y; accs[6] += s*wb.z; accs[7] += s*wb.w;
            }
        }
        const float* xr = x + (size_t)n * C;
        #pragma unroll
        for (int j = 0; j < C; j += 4) {
            float4 xv = __ldg((const float4*)(xr + j));
            #pragma unroll
            for (int jj = 0; jj < 4; jj++) {
                float s = (&xv.x)[jj];
                float4 wa = *(const float4*)&W1[j + jj][q];
                float4 wb = *(const float4*)&W1[j + jj][q + 4];
                acc[0] += s*wa.x; acc[1] += s*wa.y; acc[2] += s*wa.z; acc[3] += s*wa.w;
                acc[4] += s*wb.x; acc[5] += s*wb.y; acc[6] += s*wb.z; acc[7] += s*wb.w;
                float4 va = *(const float4*)&Ws[j + jj][q];
                float4 vb = *(const float4*)&Ws[j + jj][q + 4];
                accs[0] += s*va.x; accs[1] += s*va.y; accs[2] += s*va.z; accs[3] += s*va.w;
                accs[4] += s*vb.x; accs[5] += s*vb.y; accs[6] += s*vb.z; accs[7] += s*vb.w;
            }
        }
        size_t b = (size_t)n * C + q;
        *(float4*)(g_y1 + b)     = make_float4(acc[0], acc[1], acc[2], acc[3]);
        *(float4*)(g_y1 + b + 4) = make_float4(acc[4], acc[5], acc[6], acc[7]);
        *(float4*)(g_ys + b)     = make_float4(accs[0], accs[1], accs[2], accs[3]);
        *(float4*)(g_ys + b + 4) = make_float4(accs[4], accs[5], accs[6], accs[7]);
    }
    // ---- fused BN statistics: shfl butterfly over same-column lanes ----
    float sq[8], sqs[8];
    #pragma unroll
    for (int i = 0; i < 8; i++) { sq[i] = acc[i]*acc[i]; sqs[i] = accs[i]*accs[i]; }
    #pragma unroll
    for (int o = 4; o < 32; o <<= 1) {
        #pragma unroll
        for (int i = 0; i < 8; i++) {
            acc[i]  += __shfl_xor_sync(0xffffffffu, acc[i],  o);
            sq[i]   += __shfl_xor_sync(0xffffffffu, sq[i],   o);
            accs[i] += __shfl_xor_sync(0xffffffffu, accs[i], o);
            sqs[i]  += __shfl_xor_sync(0xffffffffu, sqs[i],  o);
        }
    }
    int lane = tid & 31, w = tid >> 5;
    if (lane < 4) {
        #pragma unroll
        for (int i = 0; i < 8; i++) {
            red[w][0][lane*8 + i] = acc[i];
            red[w][1][lane*8 + i] = sq[i];
            red[w][2][lane*8 + i] = accs[i];
            red[w][3][lane*8 + i] = sqs[i];
        }
    }
    __syncthreads();
    if (tid < 128) {
        float t = 0.f;
        #pragma unroll
        for (int ww = 0; ww < 8; ww++) t += red[ww][tid >> 5][tid & 31];
        atomicAdd(&g_stat[tid], t);
    }
}

__global__ void k_finA(const float* __restrict__ gam1, const float* __restrict__ bet1,
                       const float* __restrict__ gams, const float* __restrict__ bets) {
    int t = threadIdx.x;
    const float invn = 1.f / (float)NN;
    if (t < 32) {
        float m = g_stat[t] * invn;
        float v = g_stat[32 + t] * invn - m*m;
        float sc = gam1[t] * rsqrtf(v + BNE);
        g_bns[t] = sc; g_bns[32 + t] = bet1[t] - m*sc;
    } else if (t < 64) {
        int c = t - 32;
        float m = g_stat[64 + c] * invn;
        float v = g_stat[96 + c] * invn - m*m;
        float sc = gams[c] * rsqrtf(v + BNE);
        g_bns[64 + c] = sc; g_bns[96 + c] = bets[c] - m*sc;
    }
}

// --------------- prepB: h1 = elu(BN1(y1))  (pure elementwise) ----------------
__global__ void k_prepB() {
    int i4 = blockIdx.x * 256 + threadIdx.x;     // group of 4 elements
    if (i4 >= NN*C/4) return;
    int c4 = (i4 & 7) * 4;
    float4 y  = *(const float4*)(g_y1 + (size_t)i4 * 4);
    float4 sc = *(const float4*)(g_bns + c4);
    float4 sh = *(const float4*)(g_bns + 32 + c4);
    float v0 = y.x*sc.x + sh.x, v1 = y.y*sc.y + sh.y;
    float v2 = y.z*sc.z + sh.z, v3 = y.w*sc.w + sh.w;
    float4 h4;
    h4.x = (v0 > 0.f) ? v0 : expm1f(v0);
    h4.y = (v1 > 0.f) ? v1 : expm1f(v1);
    h4.z = (v2 > 0.f) ? v2 : expm1f(v2);
    h4.w = (v3 > 0.f) ? v3 : expm1f(v3);
    *(float4*)(g_h1 + (size_t)i4 * 4) = h4;
}

// ------------------------ edge pass 2 (conv2 K=5): gather h1 -----------------
__global__ void k_edge2() {
    int n = blockIdx.x * 8 + (threadIdx.x >> 5);
    if (n >= NN) return;
    int lane = threadIdx.x & 31;
    int beg = __ldg(&g_ptr[n]), end = __ldg(&g_ptr[n + 1]);
    float a0 = 0.f, a1 = 0.f, a2 = 0.f, a3 = 0.f, a4 = 0.f;
    int j = beg;
    for (; j + 8 <= end; j += 8) {
        uint4 m[8];
        #pragma unroll
        for (int u = 0; u < 8; u++) m[u] = __ldg(&g_m[2*(size_t)(j + u) + 1]);
        float hv[8];
        #pragma unroll
        for (int u = 0; u < 8; u++)
            hv[u] = __ldg(&g_h1[(size_t)(int)m[u].x * C + lane]);
        #pragma unroll
        for (int u = 0; u < 8; u++) {
            float2 w01 = h2f(m[u].y), w23 = h2f(m[u].z), w4x = h2f(m[u].w);
            a0 += w01.x * hv[u]; a1 += w01.y * hv[u];
            a2 += w23.x * hv[u]; a3 += w23.y * hv[u];
            a4 += w4x.x * hv[u];
        }
    }
    for (; j < end; j++) {
        uint4 m = __ldg(&g_m[2*(size_t)j + 1]);
        float hv = __ldg(&g_h1[(size_t)(int)m.x * C + lane]);
        float2 w01 = h2f(m.y), w23 = h2f(m.z), w4x = h2f(m.w);
        a0 += w01.x * hv; a1 += w01.y * hv;
        a2 += w23.x * hv; a3 += w23.y * hv;
        a4 += w4x.x * hv;
    }
    float inv = 1.f / fmaxf((float)(end - beg), 1.f);
    size_t b = (size_t)n * L1 + lane;
    g_z2[b]       = a0 * inv;
    g_z2[b + 32]  = a1 * inv;
    g_z2[b + 64]  = a2 * inv;
    g_z2[b + 96]  = a3 * inv;
    g_z2[b + 128] = a4 * inv;
}

// ------------- postB: y2 = z2@B2 + h1@root2 + b2 ; + fused BN stats ----------
__global__ void k_postB(const float* __restrict__ g2, const float* __restrict__ root2,
                        const float* __restrict__ b2) {
    __shared__ float B2[L1][C];
    __shared__ float W2[C][C];
    __shared__ float red[8][2][C];
    int tid = threadIdx.x;
    for (int idx = tid; idx < C*L1; idx += 256) {
        int i = idx / L1, r = idx % L1;
        B2[(r >> 5)*32 + i][r & 31] = g2[idx];
    }
    for (int idx = tid; idx < C*C; idx += 256)
        W2[idx >> 5][idx & 31] = root2[idx];
    __syncthreads();
    int n = blockIdx.x * 64 + (tid >> 2);
    int q = (tid & 3) * 8;
    bool valid = (n < NN);
    float acc[8] = {0,0,0,0,0,0,0,0};
    if (valid) {
        {
            float4 ba = __ldg((const float4*)(b2 + q));
            float4 bb = __ldg((const float4*)(b2 + q + 4));
            acc[0]=ba.x; acc[1]=ba.y; acc[2]=ba.z; acc[3]=ba.w;
            acc[4]=bb.x; acc[5]=bb.y; acc[6]=bb.z; acc[7]=bb.w;
        }
        const float* zr = g_z2 + (size_t)n * L1;
        #pragma unroll
        for (int j = 0; j < L1; j += 4) {
            float4 zv = __ldg((const float4*)(zr + j));
            #pragma unroll
            for (int jj = 0; jj < 4; jj++) {
                float s = (&zv.x)[jj];
                float4 wa = *(const float4*)&B2[j + jj][q];
                float4 wb = *(const float4*)&B2[j + jj][q + 4];
                acc[0] += s*wa.x; acc[1] += s*wa.y; acc[2] += s*wa.z; acc[3] += s*wa.w;
                acc[4] += s*wb.x; acc[5] += s*wb.y; acc[6] += s*wb.z; acc[7] += s*wb.w;
            }
        }
        const float* hr = g_h1 + (size_t)n * C;
        #pragma unroll
        for (int j = 0; j < C; j += 4) {
            float4 hv = __ldg((const float4*)(hr + j));
            #pragma unroll
            for (int jj = 0; jj < 4; jj++) {
                float s = (&hv.x)[jj];
                float4 wa = *(const float4*)&W2[j + jj][q];
                float4 wb = *(const float4*)&W2[j + jj][q + 4];
                acc[0] += s*wa.x; acc[1] += s*wa.y; acc[2] += s*wa.z; acc[3] += s*wa.w;
                acc[4] += s*wb.x; acc[5] += s*wb.y; acc[6] += s*wb.z; acc[7] += s*wb.w;
            }
        }
        size_t b = (size_t)n * C + q;
        *(float4*)(g_y2 + b)     = make_float4(acc[0], acc[1], acc[2], acc[3]);
        *(float4*)(g_y2 + b + 4) = make_float4(acc[4], acc[5], acc[6], acc[7]);
    }
    float sq[8];
    #pragma unroll
    for (int i = 0; i < 8; i++) sq[i] = acc[i]*acc[i];
    #pragma unroll
    for (int o = 4; o < 32; o <<= 1) {
        #pragma unroll
        for (int i = 0; i < 8; i++) {
            acc[i] += __shfl_xor_sync(0xffffffffu, acc[i], o);
            sq[i]  += __shfl_xor_sync(0xffffffffu, sq[i],  o);
        }
    }
    int lane = tid & 31, w = tid >> 5;
    if (lane < 4) {
        #pragma unroll
        for (int i = 0; i < 8; i++) {
            red[w][0][lane*8 + i] = acc[i];
            red[w][1][lane*8 + i] = sq[i];
        }
    }
    __syncthreads();
    if (tid < 64) {
        float t = 0.f;
        #pragma unroll
        for (int ww = 0; ww < 8; ww++) t += red[ww][tid >> 5][tid & 31];
        atomicAdd(&g_stat[128 + tid], t);
    }
}

__global__ void k_finB(const float* __restrict__ gam2, const float* __restrict__ bet2) {
    int t = threadIdx.x;
    if (t < 32) {
        const float invn = 1.f / (float)NN;
        float m = g_stat[128 + t] * invn;
        float v = g_stat[160 + t] * invn - m*m;
        float sc = gam2[t] * rsqrtf(v + BNE);
        g_bns[128 + t] = sc; g_bns[160 + t] = bet2[t] - m*sc;
    }
}

// ------------------- final: out = elu(BN2(y2) + BNs(ys)) ---------------------
__global__ void k_final(float* __restrict__ out) {
    int i = blockIdx.x * 256 + threadIdx.x;
    if (i >= NN*C) return;
    int c = i & 31;
    float v2 = g_y2[i] * g_bns[128 + c] + g_bns[160 + c];
    float vs = g_ys[i] * g_bns[64 + c]  + g_bns[96 + c];
    float h = v2 + vs;
    out[i] = (h > 0.f) ? h : expm1f(h);
}

// ------------------------------------------------------------------------------
extern "C" void kernel_launch(void* const* d_in, const int* in_sizes, int n_in,
                              void* d_out, int out_size) {
    (void)in_sizes; (void)n_in; (void)out_size;
    const float* x     = (const float*)d_in[0];
    const int*   ei    = (const int*)  d_in[1];
    const float* attr  = (const float*)d_in[2];
    const float* g1    = (const float*)d_in[3];
    const float* mu1   = (const float*)d_in[4];
    const float* sg1   = (const float*)d_in[5];
    const float* root1 = (const float*)d_in[6];
    const float* b1    = (const float*)d_in[7];
    const float* gam1  = (const float*)d_in[8];
    const float* bet1  = (const float*)d_in[9];
    const float* g2    = (const float*)d_in[10];
    const float* mu2   = (const float*)d_in[11];
    const float* sg2   = (const float*)d_in[12];
    const float* root2 = (const float*)d_in[13];
    const float* b2    = (const float*)d_in[14];
    const float* gam2  = (const float*)d_in[15];
    const float* bet2  = (const float*)d_in[16];
    const float* gs    = (const float*)d_in[17];
    const float* mus   = (const float*)d_in[18];
    const float* sgs   = (const float*)d_in[19];
    const float* roots = (const float*)d_in[20];
    const float* bs    = (const float*)d_in[21];
    const float* gams  = (const float*)d_in[22];
    const float* bets  = (const float*)d_in[23];
    float* out = (float*)d_out;

    const int nb_scan = (NN + 1023) / 1024;

    k_zg   <<<(NN + 255)/256, 256>>>(mu1, sg1, mu2, sg2, mus, sgs);
    k_count<<<(EE + 255)/256, 256>>>(ei);
    k_scan1<<<nb_scan, 1024>>>();
    k_scan2<<<1, 128>>>(nb_scan);
    k_scan3<<<(NN + 255)/256, 256>>>();
    k_fill <<<(EE + 255)/256, 256>>>(ei, attr);
    k_edge1<<<(NN + 7)/8,     256>>>(x);
    k_postA<<<(NN + 63)/64,   256>>>(x, g1, gs, root1, b1, roots, bs);
    k_finA <<<1, 64>>>(gam1, bet1, gams, bets);
    k_prepB<<<(NN*C/4 + 255)/256, 256>>>();
    k_edge2<<<(NN + 7)/8,     256>>>();
    k_postB<<<(NN + 63)/64,   256>>>(g2, root2, b2);
    k_finB <<<1, 32>>>(gam2, bet2);
    k_final<<<(NN*C + 255)/256, 256>>>(out);
}